// round 6
// baseline (speedup 1.0000x reference)
#include <cuda_runtime.h>
#include <math.h>

#define NN 50000
#define EE 800000

typedef unsigned long long u64;

// ---------------- f32x2 packed-FMA helpers (bit-identical fp32) ----------------
__device__ __forceinline__ u64 pack2(float lo, float hi) {
    u64 r; asm("mov.b64 %0, {%1, %2};" : "=l"(r) : "f"(lo), "f"(hi)); return r;
}
__device__ __forceinline__ void ffma2(u64& d, u64 a, u64 b) {
    asm("fma.rn.f32x2 %0, %1, %2, %0;" : "+l"(d) : "l"(a), "l"(b));
}
__device__ __forceinline__ float2 unpack2(u64 v) {
    float2 f; asm("mov.b64 {%0, %1}, %2;" : "=f"(f.x), "=f"(f.y) : "l"(v)); return f;
}

// ---------------- scratch (device globals, no runtime alloc) ----------------
__device__ int   g_deg[NN];
__device__ int   g_off[NN + 1];
__device__ int   g_cur[NN];
__device__ float g_dinv[NN];
__device__ int2  g_edge[EE];              // {src, __float_as_int(ew)}
__device__ float g_s[NN];                 // s[n] = sum of ew into n

__device__ float g_A [(size_t)NN * 128];  // conv1: [init(64) | root+b1(64)]
__device__ float g_B [(size_t)NN * 64];   // conv1 after t=0
__device__ float g_H3[(size_t)NN * 96];   // [H(0:32) | PH(32:64) | PPH(64:96)]

__device__ float g_Wp1[128 * 128];        // packed [w1_init | w1_root]
__device__ float g_W3 [96 * 40];          // folded conv2 weights [WR; Wb; Wa]
__device__ float g_bG [40];               // constant-through-A bias
__device__ float g_bR [40];               // direct bias

// ---------------- initD: zero degree ----------------
__global__ void initD_kernel() {
    int i = blockIdx.x * blockDim.x + threadIdx.x;
    if (i < NN) g_deg[i] = 0;
}

// ---------------- initW: pack Wp1 + fold conv2 weights ----------------
__global__ void initW_kernel(const float* __restrict__ w1i, const float* __restrict__ w1r,
                             const float* __restrict__ w2i, const float* __restrict__ w2d,
                             const float* __restrict__ w2r, const float* __restrict__ b2) {
    int i = blockIdx.x * blockDim.x + threadIdx.x;
    if (i < 16384) {                       // Wp1 : 128 x 128 = [w1_init | w1_root]
        int f = i >> 7, j = i & 127;
        float v;
        if (j < 64) { int k = j >> 5, h = j & 31; v = w1i[(k * 128 + f) * 32 + h]; }
        else        { int j2 = j - 64; int k = j2 >> 5, h = j2 & 31; v = w1r[(k * 128 + f) * 32 + h]; }
        g_Wp1[i] = v;
    } else if (i < 16384 + 96 * 40) {      // W3' : 96 x 40
        int i2 = i - 16384;
        int f = i2 / 40, g = i2 % 40;
        float v = 0.0f;
        if (f < 32) {
            // H rows: WR = 0.5 * sum_k w2r_k
            v = 0.5f * (w2r[f * 40 + g] + w2r[(32 + f) * 40 + g]);
        } else if (f < 64) {
            // PH rows: Wb = 0.5 * sum_k w2r_k @ w2d_k
            int fr = f - 32;
            #pragma unroll
            for (int k = 0; k < 2; ++k) {
                float s = 0.0f;
                for (int j = 0; j < 40; ++j)
                    s = fmaf(w2r[(k * 32 + fr) * 40 + j], w2d[(k * 40 + j) * 40 + g], s);
                v += s;
            }
            v *= 0.5f;
        } else {
            // PPH rows: Wa = 0.5 * sum_k w2i_k @ w2d_k
            int fr = f - 64;
            #pragma unroll
            for (int k = 0; k < 2; ++k) {
                float s = 0.0f;
                for (int j = 0; j < 40; ++j)
                    s = fmaf(w2i[(k * 32 + fr) * 40 + j], w2d[(k * 40 + j) * 40 + g], s);
                v += s;
            }
            v *= 0.5f;
        }
        g_W3[i2] = v;
    } else if (i < 16384 + 96 * 40 + 80) {
        int g = i - (16384 + 96 * 40);
        if (g < 40) {
            // bG = 0.5 * sum_k b2_k @ w2d_k
            float v = 0.0f;
            #pragma unroll
            for (int k = 0; k < 2; ++k)
                for (int j = 0; j < 40; ++j)
                    v = fmaf(b2[k * 40 + j], w2d[(k * 40 + j) * 40 + g], v);
            g_bG[g] = 0.5f * v;
        } else {
            int gg = g - 40;
            g_bR[gg] = 0.5f * (b2[gg] + b2[40 + gg]);
        }
    }
}

__global__ void hist_kernel(const int* __restrict__ col) {
    int i = (blockIdx.x * blockDim.x + threadIdx.x) * 2;
    if (i + 1 < EE) {
        int2 c = *(const int2*)&col[i];
        atomicAdd(&g_deg[c.x], 1);
        atomicAdd(&g_deg[c.y], 1);
    } else if (i < EE) {
        atomicAdd(&g_deg[col[i]], 1);
    }
}

__global__ void scan_kernel() {
    __shared__ int part[1024];
    const int t = threadIdx.x;
    const int CH = (NN + 1023) / 1024;
    int base = t * CH;
    int hi = base + CH; if (hi > NN) hi = NN;
    int sum = 0;
    for (int i = base; i < hi; ++i) sum += g_deg[i];
    part[t] = sum;
    __syncthreads();
    for (int off = 1; off < 1024; off <<= 1) {
        int v = (t >= off) ? part[t - off] : 0;
        __syncthreads();
        part[t] += v;
        __syncthreads();
    }
    int run = part[t] - sum;
    for (int i = base; i < hi; ++i) {
        int d = g_deg[i];
        g_off[i] = run;
        g_cur[i] = run;
        g_dinv[i] = (d > 0) ? rsqrtf((float)d) : 0.0f;
        run += d;
    }
    if (t == 1023) g_off[NN] = part[1023];
}

__global__ void fill_kernel(const int* __restrict__ row, const int* __restrict__ col) {
    int base = (blockIdx.x * blockDim.x + threadIdx.x) * 2;
    if (base + 1 < EE) {
        int2 r = *(const int2*)&row[base];
        int2 c = *(const int2*)&col[base];
        float dr0 = g_dinv[r.x], dc0 = g_dinv[c.x];
        float dr1 = g_dinv[r.y], dc1 = g_dinv[c.y];
        int p0 = atomicAdd(&g_cur[c.x], 1);
        int p1 = atomicAdd(&g_cur[c.y], 1);
        g_edge[p0] = make_int2(r.x, __float_as_int(dr0 * dc0));
        g_edge[p1] = make_int2(r.y, __float_as_int(dr1 * dc1));
    } else if (base < EE) {
        int r0 = row[base], c0 = col[base];
        int p0 = atomicAdd(&g_cur[c0], 1);
        g_edge[p0] = make_int2(r0, __float_as_int(g_dinv[r0] * g_dinv[c0]));
    }
}

// ---------------- GEMM1: C[N,128] = X[N,128] @ W[128,128], +b1 on cols 64..127 ----
__global__ void __launch_bounds__(256)
gemm128_kernel(const float* __restrict__ X, const float* __restrict__ W,
               const float* __restrict__ bias64, float* __restrict__ C, int nrows) {
    __shared__ float xs[16][132];
    __shared__ float ws[16][128];

    const int tid = threadIdx.x;
    const int tx  = tid & 15;
    const int ty  = tid >> 4;
    const int n0  = blockIdx.x * 128;

    u64 acc[8][4] = {};

    for (int f0 = 0; f0 < 128; f0 += 16) {
        #pragma unroll
        for (int l = 0; l < 2; ++l) {
            int idx = tid + l * 256;
            int m = idx >> 2, fq = idx & 3;
            float4 v = make_float4(0.f, 0.f, 0.f, 0.f);
            if (n0 + m < nrows)
                v = *(const float4*)&X[(size_t)(n0 + m) * 128 + f0 + fq * 4];
            xs[fq * 4 + 0][m] = v.x;
            xs[fq * 4 + 1][m] = v.y;
            xs[fq * 4 + 2][m] = v.z;
            xs[fq * 4 + 3][m] = v.w;
        }
        #pragma unroll
        for (int l = 0; l < 2; ++l) {
            int idx = tid + l * 256;
            int f = idx >> 5, j4 = idx & 31;
            *(float4*)&ws[f][j4 * 4] = *(const float4*)&W[(size_t)(f0 + f) * 128 + j4 * 4];
        }
        __syncthreads();
        #pragma unroll
        for (int f = 0; f < 16; ++f) {
            float4 xa = *(const float4*)&xs[f][ty * 8];
            float4 xb = *(const float4*)&xs[f][ty * 8 + 4];
            const u64* wp = (const u64*)&ws[f][tx * 8];
            u64 w0 = wp[0], w1 = wp[1], w2 = wp[2], w3 = wp[3];
            u64 xr;
            xr = pack2(xa.x, xa.x);
            ffma2(acc[0][0], xr, w0); ffma2(acc[0][1], xr, w1);
            ffma2(acc[0][2], xr, w2); ffma2(acc[0][3], xr, w3);
            xr = pack2(xa.y, xa.y);
            ffma2(acc[1][0], xr, w0); ffma2(acc[1][1], xr, w1);
            ffma2(acc[1][2], xr, w2); ffma2(acc[1][3], xr, w3);
            xr = pack2(xa.z, xa.z);
            ffma2(acc[2][0], xr, w0); ffma2(acc[2][1], xr, w1);
            ffma2(acc[2][2], xr, w2); ffma2(acc[2][3], xr, w3);
            xr = pack2(xa.w, xa.w);
            ffma2(acc[3][0], xr, w0); ffma2(acc[3][1], xr, w1);
            ffma2(acc[3][2], xr, w2); ffma2(acc[3][3], xr, w3);
            xr = pack2(xb.x, xb.x);
            ffma2(acc[4][0], xr, w0); ffma2(acc[4][1], xr, w1);
            ffma2(acc[4][2], xr, w2); ffma2(acc[4][3], xr, w3);
            xr = pack2(xb.y, xb.y);
            ffma2(acc[5][0], xr, w0); ffma2(acc[5][1], xr, w1);
            ffma2(acc[5][2], xr, w2); ffma2(acc[5][3], xr, w3);
            xr = pack2(xb.z, xb.z);
            ffma2(acc[6][0], xr, w0); ffma2(acc[6][1], xr, w1);
            ffma2(acc[6][2], xr, w2); ffma2(acc[6][3], xr, w3);
            xr = pack2(xb.w, xb.w);
            ffma2(acc[7][0], xr, w0); ffma2(acc[7][1], xr, w1);
            ffma2(acc[7][2], xr, w2); ffma2(acc[7][3], xr, w3);
        }
        __syncthreads();
    }

    const int jb = tx * 8;
    float bv[8];
    #pragma unroll
    for (int c = 0; c < 8; ++c) {
        int j = jb + c;
        bv[c] = (j >= 64) ? bias64[j - 64] : 0.0f;
    }
    #pragma unroll
    for (int r = 0; r < 8; ++r) {
        int n = n0 + ty * 8 + r;
        if (n >= nrows) continue;
        float2 p0 = unpack2(acc[r][0]);
        float2 p1 = unpack2(acc[r][1]);
        float2 p2 = unpack2(acc[r][2]);
        float2 p3 = unpack2(acc[r][3]);
        *(float4*)&C[(size_t)n * 128 + jb] =
            make_float4(p0.x + bv[0], p0.y + bv[1], p1.x + bv[2], p1.y + bv[3]);
        *(float4*)&C[(size_t)n * 128 + jb + 4] =
            make_float4(p2.x + bv[4], p2.y + bv[5], p3.x + bv[6], p3.y + bv[7]);
    }
}

// ---------------- prop64: B = relu(A(init) + root')  (first conv1 propagate) ----
__global__ void prop64_kernel(const float* __restrict__ src, int lds,
                              const float* __restrict__ root, int ldr,
                              float* __restrict__ out, int ldo) {
    const int gwarp = (blockIdx.x * blockDim.x + threadIdx.x) >> 5;
    const int lane  = threadIdx.x & 31;
    if (gwarp >= NN) return;
    const int n   = gwarp;
    const int beg = g_off[n];
    const int end = g_off[n + 1];

    float a0 = 0.f, a1 = 0.f;
    int e = beg;
    for (; e + 4 <= end; e += 4) {
        int2 e0 = g_edge[e],     e1 = g_edge[e + 1];
        int2 e2 = g_edge[e + 2], e3 = g_edge[e + 3];
        float w0 = __int_as_float(e0.y), w1 = __int_as_float(e1.y);
        float w2 = __int_as_float(e2.y), w3 = __int_as_float(e3.y);
        const float* p0 = src + (size_t)e0.x * lds;
        const float* p1 = src + (size_t)e1.x * lds;
        const float* p2 = src + (size_t)e2.x * lds;
        const float* p3 = src + (size_t)e3.x * lds;
        float u0 = p0[lane],      u1 = p1[lane],      u2 = p2[lane],      u3 = p3[lane];
        float v0 = p0[lane + 32], v1 = p1[lane + 32], v2 = p2[lane + 32], v3 = p3[lane + 32];
        a0 = fmaf(w0, u0, a0); a0 = fmaf(w1, u1, a0);
        a0 = fmaf(w2, u2, a0); a0 = fmaf(w3, u3, a0);
        a1 = fmaf(w0, v0, a1); a1 = fmaf(w1, v1, a1);
        a1 = fmaf(w2, v2, a1); a1 = fmaf(w3, v3, a1);
    }
    for (; e < end; ++e) {
        int2 e0 = g_edge[e];
        float w0 = __int_as_float(e0.y);
        const float* p0 = src + (size_t)e0.x * lds;
        a0 = fmaf(w0, p0[lane], a0);
        a1 = fmaf(w0, p0[lane + 32], a1);
    }

    const float* rp = root + (size_t)n * ldr;
    float* op = out + (size_t)n * ldo;
    op[lane]      = fmaxf(a0 + rp[lane],      0.f);
    op[lane + 32] = fmaxf(a1 + rp[lane + 32], 0.f);
}

// ---------------- prop64f: H = 0.5*sum_k relu(A(B)_k @ Wd_k + root_k) ----
// Gathers B (width 64), applies block-diag deep matmul AFTER aggregation
// (A(B@Wd) = A(B)@Wd), fused root+relu+stack-mean. Writes H into H3 cols 0..31.
__global__ void __launch_bounds__(256)
prop64f_kernel(const float* __restrict__ src,      // B, ld 64
               const float* __restrict__ root,     // A+64, ld 128 (includes b1)
               const float* __restrict__ w1d,      // [2][32][32]
               float* __restrict__ out) {          // H3, ld 96
    __shared__ float wd[2][32][32];
    const int tid = threadIdx.x;
    // cooperative load of 2048 weight floats
    #pragma unroll
    for (int l = 0; l < 8; ++l) {
        int idx = tid + l * 256;
        ((float*)wd)[idx] = w1d[idx];
    }
    __syncthreads();

    const int gwarp = (blockIdx.x * blockDim.x + tid) >> 5;
    const int lane  = tid & 31;
    if (gwarp >= NN) return;
    const int n   = gwarp;
    const int beg = g_off[n];
    const int end = g_off[n + 1];

    float a0 = 0.f, a1 = 0.f;
    int e = beg;
    for (; e + 4 <= end; e += 4) {
        int2 e0 = g_edge[e],     e1 = g_edge[e + 1];
        int2 e2 = g_edge[e + 2], e3 = g_edge[e + 3];
        float w0 = __int_as_float(e0.y), w1 = __int_as_float(e1.y);
        float w2 = __int_as_float(e2.y), w3 = __int_as_float(e3.y);
        const float* p0 = src + (size_t)e0.x * 64;
        const float* p1 = src + (size_t)e1.x * 64;
        const float* p2 = src + (size_t)e2.x * 64;
        const float* p3 = src + (size_t)e3.x * 64;
        float u0 = p0[lane],      u1 = p1[lane],      u2 = p2[lane],      u3 = p3[lane];
        float v0 = p0[lane + 32], v1 = p1[lane + 32], v2 = p2[lane + 32], v3 = p3[lane + 32];
        a0 = fmaf(w0, u0, a0); a0 = fmaf(w1, u1, a0);
        a0 = fmaf(w2, u2, a0); a0 = fmaf(w3, u3, a0);
        a1 = fmaf(w0, v0, a1); a1 = fmaf(w1, v1, a1);
        a1 = fmaf(w2, v2, a1); a1 = fmaf(w3, v3, a1);
    }
    for (; e < end; ++e) {
        int2 e0 = g_edge[e];
        float w0 = __int_as_float(e0.y);
        const float* p0 = src + (size_t)e0.x * 64;
        a0 = fmaf(w0, p0[lane], a0);
        a1 = fmaf(w0, p0[lane + 32], a1);
    }

    // z_k = a_k @ Wd_k via warp-broadcast matvec
    float z0 = 0.f, z1 = 0.f;
    #pragma unroll
    for (int l = 0; l < 32; ++l) {
        float b0 = __shfl_sync(0xffffffffu, a0, l);
        float b1v = __shfl_sync(0xffffffffu, a1, l);
        z0 = fmaf(b0,  wd[0][l][lane], z0);
        z1 = fmaf(b1v, wd[1][l][lane], z1);
    }

    const float* rp = root + (size_t)n * 128;
    float y0 = fmaxf(z0 + rp[lane],      0.f);
    float y1 = fmaxf(z1 + rp[lane + 32], 0.f);
    out[(size_t)n * 96 + lane] = 0.5f * (y0 + y1);
}

// ---------------- prop32: width-32 gather. SOFF = src col, DOFF = dst col.
// WITH_S: also writes s[n] = sum of ew.
template <int SOFF, int DOFF, bool WITH_S>
__global__ void prop32_kernel(const float* __restrict__ buf) {
    const int gwarp = (blockIdx.x * blockDim.x + threadIdx.x) >> 5;
    const int lane  = threadIdx.x & 31;
    if (gwarp >= NN) return;
    const int n   = gwarp;
    const int beg = g_off[n];
    const int end = g_off[n + 1];
    const float* src = buf + SOFF;

    float a0 = 0.f;
    float sw = 0.f;
    int e = beg;
    for (; e + 8 <= end; e += 8) {
        int2 ee[8];
        #pragma unroll
        for (int q = 0; q < 8; ++q) ee[q] = g_edge[e + q];
        float u[8];
        #pragma unroll
        for (int q = 0; q < 8; ++q) u[q] = src[(size_t)ee[q].x * 96 + lane];
        #pragma unroll
        for (int q = 0; q < 8; ++q) {
            float w = __int_as_float(ee[q].y);
            a0 = fmaf(w, u[q], a0);
            if (WITH_S) sw += w;
        }
    }
    for (; e < end; ++e) {
        int2 e0 = g_edge[e];
        float w = __int_as_float(e0.y);
        a0 = fmaf(w, src[(size_t)e0.x * 96 + lane], a0);
        if (WITH_S) sw += w;
    }
    float* dst = const_cast<float*>(buf) + DOFF;
    dst[(size_t)n * 96 + lane] = a0;
    if (WITH_S && lane == 0) g_s[n] = sw;
}

// ---------------- gemm96 + fused log_softmax ----------------
// out[n] = lsm( H3[n] @ W3'(96x40) + s[n]*bG + bR )
__global__ void __launch_bounds__(256)
gemm96lsm_kernel(const float* __restrict__ X,       // H3, ld 96
                 const float* __restrict__ W,       // 96 x 40
                 float* __restrict__ out, int nrows) {
    __shared__ float xs[16][132];
    __shared__ float ws[16][40];
    __shared__ float sbG[40], sbR[40];

    const int tid = threadIdx.x;
    const int tx  = tid & 7;               // 8 col groups * 5 = 40
    const int ty  = tid >> 3;              // 32 row groups * 4 = 128
    const int n0  = blockIdx.x * 128;

    if (tid < 40) { sbG[tid] = g_bG[tid]; sbR[tid] = g_bR[tid]; }

    float acc[4][5] = {};

    for (int f0 = 0; f0 < 96; f0 += 16) {
        #pragma unroll
        for (int l = 0; l < 2; ++l) {
            int idx = tid + l * 256;
            int m = idx >> 2, fq = idx & 3;
            float4 v = make_float4(0.f, 0.f, 0.f, 0.f);
            if (n0 + m < nrows)
                v = *(const float4*)&X[(size_t)(n0 + m) * 96 + f0 + fq * 4];
            xs[fq * 4 + 0][m] = v.x;
            xs[fq * 4 + 1][m] = v.y;
            xs[fq * 4 + 2][m] = v.z;
            xs[fq * 4 + 3][m] = v.w;
        }
        #pragma unroll
        for (int l = 0; l < 3; ++l) {
            int idx = tid + l * 256;
            if (idx < 640) {
                int f = idx / 40, j = idx - f * 40;
                ws[f][j] = W[(size_t)(f0 + f) * 40 + j];
            }
        }
        __syncthreads();
        #pragma unroll
        for (int f = 0; f < 16; ++f) {
            float w[5];
            #pragma unroll
            for (int c = 0; c < 5; ++c) w[c] = ws[f][tx * 5 + c];
            #pragma unroll
            for (int r = 0; r < 4; ++r) {
                float xv = xs[f][ty * 4 + r];
                #pragma unroll
                for (int c = 0; c < 5; ++c) acc[r][c] = fmaf(xv, w[c], acc[r][c]);
            }
        }
        __syncthreads();
    }

    #pragma unroll
    for (int r = 0; r < 4; ++r) {
        int n = n0 + ty * 4 + r;
        float sv = (n < nrows) ? g_s[n] : 0.f;
        float y[5];
        #pragma unroll
        for (int c = 0; c < 5; ++c) {
            int j = tx * 5 + c;
            y[c] = acc[r][c] + sv * sbG[j] + sbR[j];
        }
        float m = y[0];
        #pragma unroll
        for (int c = 1; c < 5; ++c) m = fmaxf(m, y[c]);
        #pragma unroll
        for (int o = 1; o < 8; o <<= 1) m = fmaxf(m, __shfl_xor_sync(0xffffffffu, m, o));
        float s = 0.f;
        #pragma unroll
        for (int c = 0; c < 5; ++c) s += expf(y[c] - m);
        #pragma unroll
        for (int o = 1; o < 8; o <<= 1) s += __shfl_xor_sync(0xffffffffu, s, o);
        float lse = m + logf(s);
        if (n < nrows) {
            #pragma unroll
            for (int c = 0; c < 5; ++c)
                out[(size_t)n * 40 + tx * 5 + c] = y[c] - lse;
        }
    }
}

// ---------------- launch ----------------
extern "C" void kernel_launch(void* const* d_in, const int* in_sizes, int n_in,
                              void* d_out, int out_size) {
    const float* x    = (const float*)d_in[0];
    const int*   eidx = (const int*)  d_in[1];
    const float* w1i  = (const float*)d_in[2];
    const float* w1d  = (const float*)d_in[3];
    const float* w1r  = (const float*)d_in[4];
    const float* b1   = (const float*)d_in[5];
    const float* w2i  = (const float*)d_in[6];
    const float* w2d  = (const float*)d_in[7];
    const float* w2r  = (const float*)d_in[8];
    const float* b2   = (const float*)d_in[9];
    float* outp = (float*)d_out;

    const int* row = eidx;
    const int* col = eidx + EE;

    float *A, *B, *H3, *Wp1, *W3;
    cudaGetSymbolAddress((void**)&A,   g_A);
    cudaGetSymbolAddress((void**)&B,   g_B);
    cudaGetSymbolAddress((void**)&H3,  g_H3);
    cudaGetSymbolAddress((void**)&Wp1, g_Wp1);
    cudaGetSymbolAddress((void**)&W3,  g_W3);

    static cudaStream_t s2 = nullptr;
    static cudaEvent_t  evFork = nullptr, evJoin = nullptr;
    if (s2 == nullptr) {
        cudaStreamCreateWithFlags(&s2, cudaStreamNonBlocking);
        cudaEventCreateWithFlags(&evFork, cudaEventDisableTiming);
        cudaEventCreateWithFlags(&evJoin, cudaEventDisableTiming);
    }

    const int TB = 256;
    const int nblkE2 = (EE / 2 + TB - 1) / TB;         // 1563
    const int nblkW  = (NN * 32 + TB - 1) / TB;        // 6250 (warp per node)
    const int gR = (NN + 127) / 128;                   // 391 row tiles

    // ---- fork: weights + gemm128 on s2, graph build on main stream ----
    cudaEventRecord(evFork, 0);
    cudaStreamWaitEvent(s2, evFork, 0);

    initW_kernel<<<(16384 + 96 * 40 + 80 + TB - 1) / TB, TB, 0, s2>>>(w1i, w1r, w2i, w2d, w2r, b2);
    gemm128_kernel<<<gR, TB, 0, s2>>>(x, Wp1, b1, A, NN);
    cudaEventRecord(evJoin, s2);

    initD_kernel<<<(NN + TB - 1) / TB, TB>>>();
    hist_kernel<<<nblkE2, TB>>>(col);
    scan_kernel<<<1, 1024>>>();
    fill_kernel<<<nblkE2, TB>>>(row, col);

    cudaStreamWaitEvent(0, evJoin, 0);

    // ---- conv1 ----
    prop64_kernel<<<nblkW, TB>>>(A, 128, A + 64, 128, B, 64);
    prop64f_kernel<<<nblkW, TB>>>(B, A + 64, w1d, H3);      // H -> H3 cols 0..31

    // ---- conv2 (fully folded) ----
    prop32_kernel<0, 32, true ><<<nblkW, TB>>>(H3);         // PH  = A(H),  + s[n]
    prop32_kernel<32, 64, false><<<nblkW, TB>>>(H3);        // PPH = A(PH)
    gemm96lsm_kernel<<<gR, TB>>>(H3, W3, outp, NN);
}

// round 7
// speedup vs baseline: 1.0651x; 1.0651x over previous
#include <cuda_runtime.h>
#include <math.h>

#define NN 50000
#define EE 800000

typedef unsigned long long u64;

// ---------------- f32x2 packed-FMA helpers (bit-identical fp32) ----------------
__device__ __forceinline__ u64 pack2(float lo, float hi) {
    u64 r; asm("mov.b64 %0, {%1, %2};" : "=l"(r) : "f"(lo), "f"(hi)); return r;
}
__device__ __forceinline__ void ffma2(u64& d, u64 a, u64 b) {
    asm("fma.rn.f32x2 %0, %1, %2, %0;" : "+l"(d) : "l"(a), "l"(b));
}
__device__ __forceinline__ float2 unpack2(u64 v) {
    float2 f; asm("mov.b64 {%0, %1}, %2;" : "=f"(f.x), "=f"(f.y) : "l"(v)); return f;
}

// ---------------- scratch (device globals, no runtime alloc) ----------------
__device__ int   g_deg[NN];
__device__ int   g_off[NN + 1];
__device__ int   g_cur[NN];
__device__ float g_dinv[NN];
__device__ int2  g_edge[EE];              // {src, __float_as_int(ew)}
__device__ float g_s[NN];                 // s[n] = sum of ew into n

__device__ float g_A [(size_t)NN * 128];  // conv1: [init(64) | root+b1(64)]
__device__ float g_B [(size_t)NN * 64];   // conv1 after t=0
__device__ float g_H3[(size_t)NN * 128];  // [H(0:32) | PH(32:64) | PPH(64:96) | pad]

__device__ float g_Wp1[128 * 128];        // packed [w1_init | w1_root]
__device__ float g_W3 [96 * 40];          // folded conv2 weights [WR; Wb; Wa]
__device__ float g_bG [40];               // constant-through-A bias
__device__ float g_bR [40];               // direct bias

// ---------------- init: zero degree + pack Wp1 + fold conv2 weights ----------------
__global__ void init_kernel(const float* __restrict__ w1i, const float* __restrict__ w1r,
                            const float* __restrict__ w2i, const float* __restrict__ w2d,
                            const float* __restrict__ w2r, const float* __restrict__ b2) {
    int i = blockIdx.x * blockDim.x + threadIdx.x;
    if (i < NN) g_deg[i] = 0;
    if (i < 16384) {                       // Wp1 : 128 x 128 = [w1_init | w1_root]
        int f = i >> 7, j = i & 127;
        float v;
        if (j < 64) { int k = j >> 5, h = j & 31; v = w1i[(k * 128 + f) * 32 + h]; }
        else        { int j2 = j - 64; int k = j2 >> 5, h = j2 & 31; v = w1r[(k * 128 + f) * 32 + h]; }
        g_Wp1[i] = v;
    } else if (i < 16384 + 96 * 40) {      // W3' : 96 x 40
        int i2 = i - 16384;
        int f = i2 / 40, g = i2 % 40;
        float v = 0.0f;
        if (f < 32) {
            v = 0.5f * (w2r[f * 40 + g] + w2r[(32 + f) * 40 + g]);
        } else if (f < 64) {
            int fr = f - 32;
            #pragma unroll
            for (int k = 0; k < 2; ++k) {
                float s = 0.0f;
                for (int j = 0; j < 40; ++j)
                    s = fmaf(w2r[(k * 32 + fr) * 40 + j], w2d[(k * 40 + j) * 40 + g], s);
                v += s;
            }
            v *= 0.5f;
        } else {
            int fr = f - 64;
            #pragma unroll
            for (int k = 0; k < 2; ++k) {
                float s = 0.0f;
                for (int j = 0; j < 40; ++j)
                    s = fmaf(w2i[(k * 32 + fr) * 40 + j], w2d[(k * 40 + j) * 40 + g], s);
                v += s;
            }
            v *= 0.5f;
        }
        g_W3[i2] = v;
    } else if (i < 16384 + 96 * 40 + 80) {
        int g = i - (16384 + 96 * 40);
        if (g < 40) {
            float v = 0.0f;
            #pragma unroll
            for (int k = 0; k < 2; ++k)
                for (int j = 0; j < 40; ++j)
                    v = fmaf(b2[k * 40 + j], w2d[(k * 40 + j) * 40 + g], v);
            g_bG[g] = 0.5f * v;
        } else {
            int gg = g - 40;
            g_bR[gg] = 0.5f * (b2[gg] + b2[40 + gg]);
        }
    }
}

__global__ void hist_kernel(const int* __restrict__ col) {
    int i = (blockIdx.x * blockDim.x + threadIdx.x) * 2;
    if (i + 1 < EE) {
        int2 c = *(const int2*)&col[i];
        atomicAdd(&g_deg[c.x], 1);
        atomicAdd(&g_deg[c.y], 1);
    } else if (i < EE) {
        atomicAdd(&g_deg[col[i]], 1);
    }
}

__global__ void scan_kernel() {
    __shared__ int part[1024];
    const int t = threadIdx.x;
    const int CH = (NN + 1023) / 1024;
    int base = t * CH;
    int hi = base + CH; if (hi > NN) hi = NN;
    int sum = 0;
    for (int i = base; i < hi; ++i) sum += g_deg[i];
    part[t] = sum;
    __syncthreads();
    for (int off = 1; off < 1024; off <<= 1) {
        int v = (t >= off) ? part[t - off] : 0;
        __syncthreads();
        part[t] += v;
        __syncthreads();
    }
    int run = part[t] - sum;
    for (int i = base; i < hi; ++i) {
        int d = g_deg[i];
        g_off[i] = run;
        g_cur[i] = run;
        g_dinv[i] = (d > 0) ? rsqrtf((float)d) : 0.0f;
        run += d;
    }
    if (t == 1023) g_off[NN] = part[1023];
}

__global__ void fill_kernel(const int* __restrict__ row, const int* __restrict__ col) {
    int base = (blockIdx.x * blockDim.x + threadIdx.x) * 2;
    if (base + 1 < EE) {
        int2 r = *(const int2*)&row[base];
        int2 c = *(const int2*)&col[base];
        float dr0 = g_dinv[r.x], dc0 = g_dinv[c.x];
        float dr1 = g_dinv[r.y], dc1 = g_dinv[c.y];
        int p0 = atomicAdd(&g_cur[c.x], 1);
        int p1 = atomicAdd(&g_cur[c.y], 1);
        g_edge[p0] = make_int2(r.x, __float_as_int(dr0 * dc0));
        g_edge[p1] = make_int2(r.y, __float_as_int(dr1 * dc1));
    } else if (base < EE) {
        int r0 = row[base], c0 = col[base];
        int p0 = atomicAdd(&g_cur[c0], 1);
        g_edge[p0] = make_int2(r0, __float_as_int(g_dinv[r0] * g_dinv[c0]));
    }
}

// ---------------- GEMM1: C[N,128] = X[N,128] @ W[128,128], +b1 on cols 64..127 ----
__global__ void __launch_bounds__(256)
gemm128_kernel(const float* __restrict__ X, const float* __restrict__ W,
               const float* __restrict__ bias64, float* __restrict__ C, int nrows) {
    __shared__ float xs[16][132];
    __shared__ float ws[16][128];

    const int tid = threadIdx.x;
    const int tx  = tid & 15;
    const int ty  = tid >> 4;
    const int n0  = blockIdx.x * 128;

    u64 acc[8][4] = {};

    for (int f0 = 0; f0 < 128; f0 += 16) {
        #pragma unroll
        for (int l = 0; l < 2; ++l) {
            int idx = tid + l * 256;
            int m = idx >> 2, fq = idx & 3;
            float4 v = make_float4(0.f, 0.f, 0.f, 0.f);
            if (n0 + m < nrows)
                v = *(const float4*)&X[(size_t)(n0 + m) * 128 + f0 + fq * 4];
            xs[fq * 4 + 0][m] = v.x;
            xs[fq * 4 + 1][m] = v.y;
            xs[fq * 4 + 2][m] = v.z;
            xs[fq * 4 + 3][m] = v.w;
        }
        #pragma unroll
        for (int l = 0; l < 2; ++l) {
            int idx = tid + l * 256;
            int f = idx >> 5, j4 = idx & 31;
            *(float4*)&ws[f][j4 * 4] = *(const float4*)&W[(size_t)(f0 + f) * 128 + j4 * 4];
        }
        __syncthreads();
        #pragma unroll
        for (int f = 0; f < 16; ++f) {
            float4 xa = *(const float4*)&xs[f][ty * 8];
            float4 xb = *(const float4*)&xs[f][ty * 8 + 4];
            const u64* wp = (const u64*)&ws[f][tx * 8];
            u64 w0 = wp[0], w1 = wp[1], w2 = wp[2], w3 = wp[3];
            u64 xr;
            xr = pack2(xa.x, xa.x);
            ffma2(acc[0][0], xr, w0); ffma2(acc[0][1], xr, w1);
            ffma2(acc[0][2], xr, w2); ffma2(acc[0][3], xr, w3);
            xr = pack2(xa.y, xa.y);
            ffma2(acc[1][0], xr, w0); ffma2(acc[1][1], xr, w1);
            ffma2(acc[1][2], xr, w2); ffma2(acc[1][3], xr, w3);
            xr = pack2(xa.z, xa.z);
            ffma2(acc[2][0], xr, w0); ffma2(acc[2][1], xr, w1);
            ffma2(acc[2][2], xr, w2); ffma2(acc[2][3], xr, w3);
            xr = pack2(xa.w, xa.w);
            ffma2(acc[3][0], xr, w0); ffma2(acc[3][1], xr, w1);
            ffma2(acc[3][2], xr, w2); ffma2(acc[3][3], xr, w3);
            xr = pack2(xb.x, xb.x);
            ffma2(acc[4][0], xr, w0); ffma2(acc[4][1], xr, w1);
            ffma2(acc[4][2], xr, w2); ffma2(acc[4][3], xr, w3);
            xr = pack2(xb.y, xb.y);
            ffma2(acc[5][0], xr, w0); ffma2(acc[5][1], xr, w1);
            ffma2(acc[5][2], xr, w2); ffma2(acc[5][3], xr, w3);
            xr = pack2(xb.z, xb.z);
            ffma2(acc[6][0], xr, w0); ffma2(acc[6][1], xr, w1);
            ffma2(acc[6][2], xr, w2); ffma2(acc[6][3], xr, w3);
            xr = pack2(xb.w, xb.w);
            ffma2(acc[7][0], xr, w0); ffma2(acc[7][1], xr, w1);
            ffma2(acc[7][2], xr, w2); ffma2(acc[7][3], xr, w3);
        }
        __syncthreads();
    }

    const int jb = tx * 8;
    float bv[8];
    #pragma unroll
    for (int c = 0; c < 8; ++c) {
        int j = jb + c;
        bv[c] = (j >= 64) ? bias64[j - 64] : 0.0f;
    }
    #pragma unroll
    for (int r = 0; r < 8; ++r) {
        int n = n0 + ty * 8 + r;
        if (n >= nrows) continue;
        float2 p0 = unpack2(acc[r][0]);
        float2 p1 = unpack2(acc[r][1]);
        float2 p2 = unpack2(acc[r][2]);
        float2 p3 = unpack2(acc[r][3]);
        *(float4*)&C[(size_t)n * 128 + jb] =
            make_float4(p0.x + bv[0], p0.y + bv[1], p1.x + bv[2], p1.y + bv[3]);
        *(float4*)&C[(size_t)n * 128 + jb + 4] =
            make_float4(p2.x + bv[4], p2.y + bv[5], p3.x + bv[6], p3.y + bv[7]);
    }
}

// ---------------- prop64: B = relu(A(init) + root')  [vectorized gather] ----
// lanes split: eg = lane>>4 selects edge of a pair, cg = lane&15 selects float4.
__global__ void prop64_kernel(const float* __restrict__ src,   // A, ld 128, cols 0..63
                              const float* __restrict__ root,  // A+64, ld 128
                              float* __restrict__ out) {       // B, ld 64
    const int gwarp = (blockIdx.x * blockDim.x + threadIdx.x) >> 5;
    const int lane  = threadIdx.x & 31;
    if (gwarp >= NN) return;
    const int n   = gwarp;
    const int beg = g_off[n];
    const int end = g_off[n + 1];
    const int eg = lane >> 4, cg = lane & 15;

    float4 acc = make_float4(0.f, 0.f, 0.f, 0.f);
    int e = beg;
    for (; e + 4 <= end; e += 4) {                    // 4 edges per iter (2 per instr)
        int2 ea = g_edge[e + eg];
        int2 eb = g_edge[e + 2 + eg];
        float4 va = ((const float4*)(src + (size_t)ea.x * 128))[cg];
        float4 vb = ((const float4*)(src + (size_t)eb.x * 128))[cg];
        float wa = __int_as_float(ea.y), wb = __int_as_float(eb.y);
        acc.x = fmaf(wa, va.x, acc.x); acc.y = fmaf(wa, va.y, acc.y);
        acc.z = fmaf(wa, va.z, acc.z); acc.w = fmaf(wa, va.w, acc.w);
        acc.x = fmaf(wb, vb.x, acc.x); acc.y = fmaf(wb, vb.y, acc.y);
        acc.z = fmaf(wb, vb.z, acc.z); acc.w = fmaf(wb, vb.w, acc.w);
    }
    for (; e < end; e += 2) {                         // tail, 1-2 edges
        int2 ea = (e + eg < end) ? g_edge[e + eg] : make_int2(0, 0);
        float4 va = ((const float4*)(src + (size_t)ea.x * 128))[cg];
        float wa = __int_as_float(ea.y);
        acc.x = fmaf(wa, va.x, acc.x); acc.y = fmaf(wa, va.y, acc.y);
        acc.z = fmaf(wa, va.z, acc.z); acc.w = fmaf(wa, va.w, acc.w);
    }
    // reduce over the 2 edge groups
    acc.x += __shfl_xor_sync(0xffffffffu, acc.x, 16);
    acc.y += __shfl_xor_sync(0xffffffffu, acc.y, 16);
    acc.z += __shfl_xor_sync(0xffffffffu, acc.z, 16);
    acc.w += __shfl_xor_sync(0xffffffffu, acc.w, 16);

    if (lane < 16) {
        float4 rp = ((const float4*)(root + (size_t)n * 128))[cg];
        float4 y = make_float4(fmaxf(acc.x + rp.x, 0.f), fmaxf(acc.y + rp.y, 0.f),
                               fmaxf(acc.z + rp.z, 0.f), fmaxf(acc.w + rp.w, 0.f));
        ((float4*)(out + (size_t)n * 64))[cg] = y;
    }
}

// ---------------- prop64f: H = 0.5*sum_k relu(A(B)_k @ Wd_k + root_k) ----
// Vectorized gather of B, block-diag deep matvec applied after aggregation.
__global__ void __launch_bounds__(256)
prop64f_kernel(const float* __restrict__ src,      // B, ld 64
               const float* __restrict__ root,     // A+64, ld 128 (includes b1)
               const float* __restrict__ w1d,      // [2][32][32]
               float* __restrict__ out) {          // H3, ld 128, cols 0..31
    __shared__ float wd[2][32][32];
    __shared__ float sm[8][64];
    const int tid = threadIdx.x;
    #pragma unroll
    for (int l = 0; l < 8; ++l)
        ((float*)wd)[tid + l * 256] = w1d[tid + l * 256];
    __syncthreads();

    const int gwarp = (blockIdx.x * blockDim.x + tid) >> 5;
    const int lane  = tid & 31;
    const int wwarp = tid >> 5;
    if (gwarp >= NN) return;
    const int n   = gwarp;
    const int beg = g_off[n];
    const int end = g_off[n + 1];
    const int eg = lane >> 4, cg = lane & 15;

    float4 acc = make_float4(0.f, 0.f, 0.f, 0.f);
    int e = beg;
    for (; e + 4 <= end; e += 4) {
        int2 ea = g_edge[e + eg];
        int2 eb = g_edge[e + 2 + eg];
        float4 va = ((const float4*)(src + (size_t)ea.x * 64))[cg];
        float4 vb = ((const float4*)(src + (size_t)eb.x * 64))[cg];
        float wa = __int_as_float(ea.y), wb = __int_as_float(eb.y);
        acc.x = fmaf(wa, va.x, acc.x); acc.y = fmaf(wa, va.y, acc.y);
        acc.z = fmaf(wa, va.z, acc.z); acc.w = fmaf(wa, va.w, acc.w);
        acc.x = fmaf(wb, vb.x, acc.x); acc.y = fmaf(wb, vb.y, acc.y);
        acc.z = fmaf(wb, vb.z, acc.z); acc.w = fmaf(wb, vb.w, acc.w);
    }
    for (; e < end; e += 2) {
        int2 ea = (e + eg < end) ? g_edge[e + eg] : make_int2(0, 0);
        float4 va = ((const float4*)(src + (size_t)ea.x * 64))[cg];
        float wa = __int_as_float(ea.y);
        acc.x = fmaf(wa, va.x, acc.x); acc.y = fmaf(wa, va.y, acc.y);
        acc.z = fmaf(wa, va.z, acc.z); acc.w = fmaf(wa, va.w, acc.w);
    }
    acc.x += __shfl_xor_sync(0xffffffffu, acc.x, 16);
    acc.y += __shfl_xor_sync(0xffffffffu, acc.y, 16);
    acc.z += __shfl_xor_sync(0xffffffffu, acc.z, 16);
    acc.w += __shfl_xor_sync(0xffffffffu, acc.w, 16);

    // stage to scalar layout
    if (lane < 16) ((float4*)sm[wwarp])[cg] = acc;
    __syncwarp();
    float a0 = sm[wwarp][lane];
    float a1 = sm[wwarp][lane + 32];

    // z_k = a_k @ Wd_k via warp-broadcast matvec
    float z0 = 0.f, z1 = 0.f;
    #pragma unroll
    for (int l = 0; l < 32; ++l) {
        float b0  = __shfl_sync(0xffffffffu, a0, l);
        float b1v = __shfl_sync(0xffffffffu, a1, l);
        z0 = fmaf(b0,  wd[0][l][lane], z0);
        z1 = fmaf(b1v, wd[1][l][lane], z1);
    }

    const float* rp = root + (size_t)n * 128;
    float y0 = fmaxf(z0 + rp[lane],      0.f);
    float y1 = fmaxf(z1 + rp[lane + 32], 0.f);
    out[(size_t)n * 128 + lane] = 0.5f * (y0 + y1);
}

// ---------------- prop32: vectorized width-32 gather within H3 (ld 128) ----
// eg = lane>>3 selects one of 4 edges, cg = lane&7 selects float4.
template <int SOFF, int DOFF, bool WITH_S>
__global__ void prop32_kernel(float* __restrict__ buf) {
    const int gwarp = (blockIdx.x * blockDim.x + threadIdx.x) >> 5;
    const int lane  = threadIdx.x & 31;
    if (gwarp >= NN) return;
    const int n   = gwarp;
    const int beg = g_off[n];
    const int end = g_off[n + 1];
    const int eg = lane >> 3, cg = lane & 7;
    const float* src = buf + SOFF;

    float4 acc = make_float4(0.f, 0.f, 0.f, 0.f);
    float sw = 0.f;
    int e = beg;
    for (; e + 8 <= end; e += 8) {                    // 8 edges per iter (4 per instr)
        int2 ea = g_edge[e + eg];
        int2 eb = g_edge[e + 4 + eg];
        float4 va = ((const float4*)(src + (size_t)ea.x * 128))[cg];
        float4 vb = ((const float4*)(src + (size_t)eb.x * 128))[cg];
        float wa = __int_as_float(ea.y), wb = __int_as_float(eb.y);
        acc.x = fmaf(wa, va.x, acc.x); acc.y = fmaf(wa, va.y, acc.y);
        acc.z = fmaf(wa, va.z, acc.z); acc.w = fmaf(wa, va.w, acc.w);
        acc.x = fmaf(wb, vb.x, acc.x); acc.y = fmaf(wb, vb.y, acc.y);
        acc.z = fmaf(wb, vb.z, acc.z); acc.w = fmaf(wb, vb.w, acc.w);
        if (WITH_S) sw += wa + wb;
    }
    for (; e < end; e += 4) {                         // tail, 1-4 edges
        int2 ea = (e + eg < end) ? g_edge[e + eg] : make_int2(0, 0);
        float4 va = ((const float4*)(src + (size_t)ea.x * 128))[cg];
        float wa = __int_as_float(ea.y);
        acc.x = fmaf(wa, va.x, acc.x); acc.y = fmaf(wa, va.y, acc.y);
        acc.z = fmaf(wa, va.z, acc.z); acc.w = fmaf(wa, va.w, acc.w);
        if (WITH_S) sw += wa;
    }
    // reduce over the 4 edge groups
    #pragma unroll
    for (int o = 8; o <= 16; o <<= 1) {
        acc.x += __shfl_xor_sync(0xffffffffu, acc.x, o);
        acc.y += __shfl_xor_sync(0xffffffffu, acc.y, o);
        acc.z += __shfl_xor_sync(0xffffffffu, acc.z, o);
        acc.w += __shfl_xor_sync(0xffffffffu, acc.w, o);
        if (WITH_S) sw += __shfl_xor_sync(0xffffffffu, sw, o);
    }
    if (lane < 8)
        ((float4*)(buf + (size_t)n * 128 + DOFF))[cg] = acc;
    if (WITH_S && lane == 0) g_s[n] = sw;
}

// ---------------- gemm96 + fused log_softmax ----------------
__global__ void __launch_bounds__(256)
gemm96lsm_kernel(const float* __restrict__ X,       // H3, ld 128 (cols 0..95)
                 const float* __restrict__ W,       // 96 x 40
                 float* __restrict__ out, int nrows) {
    __shared__ float xs[16][132];
    __shared__ float ws[16][40];
    __shared__ float sbG[40], sbR[40];

    const int tid = threadIdx.x;
    const int tx  = tid & 7;
    const int ty  = tid >> 3;
    const int n0  = blockIdx.x * 128;

    if (tid < 40) { sbG[tid] = g_bG[tid]; sbR[tid] = g_bR[tid]; }

    float acc[4][5] = {};

    for (int f0 = 0; f0 < 96; f0 += 16) {
        #pragma unroll
        for (int l = 0; l < 2; ++l) {
            int idx = tid + l * 256;
            int m = idx >> 2, fq = idx & 3;
            float4 v = make_float4(0.f, 0.f, 0.f, 0.f);
            if (n0 + m < nrows)
                v = *(const float4*)&X[(size_t)(n0 + m) * 128 + f0 + fq * 4];
            xs[fq * 4 + 0][m] = v.x;
            xs[fq * 4 + 1][m] = v.y;
            xs[fq * 4 + 2][m] = v.z;
            xs[fq * 4 + 3][m] = v.w;
        }
        #pragma unroll
        for (int l = 0; l < 3; ++l) {
            int idx = tid + l * 256;
            if (idx < 640) {
                int f = idx / 40, j = idx - f * 40;
                ws[f][j] = W[(size_t)(f0 + f) * 40 + j];
            }
        }
        __syncthreads();
        #pragma unroll
        for (int f = 0; f < 16; ++f) {
            float w[5];
            #pragma unroll
            for (int c = 0; c < 5; ++c) w[c] = ws[f][tx * 5 + c];
            #pragma unroll
            for (int r = 0; r < 4; ++r) {
                float xv = xs[f][ty * 4 + r];
                #pragma unroll
                for (int c = 0; c < 5; ++c) acc[r][c] = fmaf(xv, w[c], acc[r][c]);
            }
        }
        __syncthreads();
    }

    #pragma unroll
    for (int r = 0; r < 4; ++r) {
        int n = n0 + ty * 4 + r;
        float sv = (n < nrows) ? g_s[n] : 0.f;
        float y[5];
        #pragma unroll
        for (int c = 0; c < 5; ++c) {
            int j = tx * 5 + c;
            y[c] = acc[r][c] + sv * sbG[j] + sbR[j];
        }
        float m = y[0];
        #pragma unroll
        for (int c = 1; c < 5; ++c) m = fmaxf(m, y[c]);
        #pragma unroll
        for (int o = 1; o < 8; o <<= 1) m = fmaxf(m, __shfl_xor_sync(0xffffffffu, m, o));
        float s = 0.f;
        #pragma unroll
        for (int c = 0; c < 5; ++c) s += expf(y[c] - m);
        #pragma unroll
        for (int o = 1; o < 8; o <<= 1) s += __shfl_xor_sync(0xffffffffu, s, o);
        float lse = m + logf(s);
        if (n < nrows) {
            #pragma unroll
            for (int c = 0; c < 5; ++c)
                out[(size_t)n * 40 + tx * 5 + c] = y[c] - lse;
        }
    }
}

// ---------------- launch ----------------
extern "C" void kernel_launch(void* const* d_in, const int* in_sizes, int n_in,
                              void* d_out, int out_size) {
    const float* x    = (const float*)d_in[0];
    const int*   eidx = (const int*)  d_in[1];
    const float* w1i  = (const float*)d_in[2];
    const float* w1d  = (const float*)d_in[3];
    const float* w1r  = (const float*)d_in[4];
    const float* b1   = (const float*)d_in[5];
    const float* w2i  = (const float*)d_in[6];
    const float* w2d  = (const float*)d_in[7];
    const float* w2r  = (const float*)d_in[8];
    const float* b2   = (const float*)d_in[9];
    float* outp = (float*)d_out;

    const int* row = eidx;
    const int* col = eidx + EE;

    float *A, *B, *H3, *Wp1, *W3;
    cudaGetSymbolAddress((void**)&A,   g_A);
    cudaGetSymbolAddress((void**)&B,   g_B);
    cudaGetSymbolAddress((void**)&H3,  g_H3);
    cudaGetSymbolAddress((void**)&Wp1, g_Wp1);
    cudaGetSymbolAddress((void**)&W3,  g_W3);

    static cudaStream_t s2 = nullptr;
    static cudaEvent_t  evFork = nullptr, evJoin = nullptr;
    if (s2 == nullptr) {
        cudaStreamCreateWithFlags(&s2, cudaStreamNonBlocking);
        cudaEventCreateWithFlags(&evFork, cudaEventDisableTiming);
        cudaEventCreateWithFlags(&evJoin, cudaEventDisableTiming);
    }

    const int TB = 256;
    const int nblkE2 = (EE / 2 + TB - 1) / TB;         // 1563
    const int nblkW  = (NN * 32 + TB - 1) / TB;        // 6250 (warp per node)
    const int gR = (NN + 127) / 128;                   // 391 row tiles

    // init (zero deg + all weight folding) on main, then fork gemm128 to s2
    init_kernel<<<(NN + TB - 1) / TB, TB>>>(w1i, w1r, w2i, w2d, w2r, b2);
    cudaEventRecord(evFork, 0);
    cudaStreamWaitEvent(s2, evFork, 0);
    gemm128_kernel<<<gR, TB, 0, s2>>>(x, Wp1, b1, A, NN);
    cudaEventRecord(evJoin, s2);

    hist_kernel<<<nblkE2, TB>>>(col);
    scan_kernel<<<1, 1024>>>();
    fill_kernel<<<nblkE2, TB>>>(row, col);

    cudaStreamWaitEvent(0, evJoin, 0);

    // ---- conv1 ----
    prop64_kernel<<<nblkW, TB>>>(A, A + 64, B);
    prop64f_kernel<<<nblkW, TB>>>(B, A + 64, w1d, H3);       // H -> H3 cols 0..31

    // ---- conv2 (fully folded) ----
    prop32_kernel<0, 32, true ><<<nblkW, TB>>>(H3);          // PH  = A(H),  + s[n]
    prop32_kernel<32, 64, false><<<nblkW, TB>>>(H3);         // PPH = A(PH)
    gemm96lsm_kernel<<<gR, TB>>>(H3, W3, outp, NN);
}

// round 8
// speedup vs baseline: 1.6165x; 1.5178x over previous
#include <cuda_runtime.h>
#include <math.h>

#define NN 50000
#define EE 800000
#define NBLK_SCAN 196            // ceil(50000/256)

typedef unsigned long long u64;

// ---------------- f32x2 packed-FMA helpers (bit-identical fp32) ----------------
__device__ __forceinline__ u64 pack2(float lo, float hi) {
    u64 r; asm("mov.b64 %0, {%1, %2};" : "=l"(r) : "f"(lo), "f"(hi)); return r;
}
__device__ __forceinline__ void ffma2(u64& d, u64 a, u64 b) {
    asm("fma.rn.f32x2 %0, %1, %2, %0;" : "+l"(d) : "l"(a), "l"(b));
}
__device__ __forceinline__ float2 unpack2(u64 v) {
    float2 f; asm("mov.b64 {%0, %1}, %2;" : "=f"(f.x), "=f"(f.y) : "l"(v)); return f;
}

// ---------------- scratch (device globals, no runtime alloc) ----------------
__device__ int   g_deg[NN];
__device__ int   g_off[NN + 1];
__device__ int   g_cur[NN];
__device__ float g_dinv[NN];
__device__ int   g_part[NBLK_SCAN];
__device__ int2  g_edge[EE];              // {src, __float_as_int(ew)}
__device__ float g_s[NN];                 // s[n] = sum of ew into n

__device__ float g_A [(size_t)NN * 128];  // conv1: [init(64) | root+b1(64)]
__device__ float g_B [(size_t)NN * 64];   // conv1 after t=0
__device__ float g_H3[(size_t)NN * 128];  // [H(0:32) | PH(32:64) | PPH(64:96) | pad]

__device__ float g_Wp1[128 * 128];        // packed [w1_init | w1_root]
__device__ float g_W3 [96 * 40];          // folded conv2 weights [WR; Wb; Wa]
__device__ float g_bG [40];               // constant-through-A bias
__device__ float g_bR [40];               // direct bias

// ---------------- init: zero degree + pack Wp1 + fold conv2 weights ----------------
__global__ void init_kernel(const float* __restrict__ w1i, const float* __restrict__ w1r,
                            const float* __restrict__ w2i, const float* __restrict__ w2d,
                            const float* __restrict__ w2r, const float* __restrict__ b2) {
    int i = blockIdx.x * blockDim.x + threadIdx.x;
    if (i < NN) g_deg[i] = 0;
    if (i < 16384) {                       // Wp1 : 128 x 128 = [w1_init | w1_root]
        int f = i >> 7, j = i & 127;
        float v;
        if (j < 64) { int k = j >> 5, h = j & 31; v = w1i[(k * 128 + f) * 32 + h]; }
        else        { int j2 = j - 64; int k = j2 >> 5, h = j2 & 31; v = w1r[(k * 128 + f) * 32 + h]; }
        g_Wp1[i] = v;
    } else if (i < 16384 + 96 * 40) {      // W3' : 96 x 40
        int i2 = i - 16384;
        int f = i2 / 40, g = i2 % 40;
        float v = 0.0f;
        if (f < 32) {
            v = 0.5f * (w2r[f * 40 + g] + w2r[(32 + f) * 40 + g]);
        } else if (f < 64) {
            int fr = f - 32;
            #pragma unroll
            for (int k = 0; k < 2; ++k) {
                float s = 0.0f;
                for (int j = 0; j < 40; ++j)
                    s = fmaf(w2r[(k * 32 + fr) * 40 + j], w2d[(k * 40 + j) * 40 + g], s);
                v += s;
            }
            v *= 0.5f;
        } else {
            int fr = f - 64;
            #pragma unroll
            for (int k = 0; k < 2; ++k) {
                float s = 0.0f;
                for (int j = 0; j < 40; ++j)
                    s = fmaf(w2i[(k * 32 + fr) * 40 + j], w2d[(k * 40 + j) * 40 + g], s);
                v += s;
            }
            v *= 0.5f;
        }
        g_W3[i2] = v;
    } else if (i < 16384 + 96 * 40 + 80) {
        int g = i - (16384 + 96 * 40);
        if (g < 40) {
            float v = 0.0f;
            #pragma unroll
            for (int k = 0; k < 2; ++k)
                for (int j = 0; j < 40; ++j)
                    v = fmaf(b2[k * 40 + j], w2d[(k * 40 + j) * 40 + g], v);
            g_bG[g] = 0.5f * v;
        } else {
            int gg = g - 40;
            g_bR[gg] = 0.5f * (b2[gg] + b2[40 + gg]);
        }
    }
}

__global__ void hist_kernel(const int* __restrict__ col) {
    int i = (blockIdx.x * blockDim.x + threadIdx.x) * 2;
    if (i + 1 < EE) {
        int2 c = *(const int2*)&col[i];
        atomicAdd(&g_deg[c.x], 1);
        atomicAdd(&g_deg[c.y], 1);
    } else if (i < EE) {
        atomicAdd(&g_deg[col[i]], 1);
    }
}

// ---------------- multi-block scan, phase A: block-reduce degrees + dinv ----------------
__global__ void scanA_kernel() {
    __shared__ int sm[256];
    const int tid = threadIdx.x;
    const int i = blockIdx.x * 256 + tid;
    int d = (i < NN) ? g_deg[i] : 0;
    if (i < NN) g_dinv[i] = (d > 0) ? rsqrtf((float)d) : 0.0f;
    sm[tid] = d;
    __syncthreads();
    #pragma unroll
    for (int off = 128; off > 0; off >>= 1) {
        if (tid < off) sm[tid] += sm[tid + off];
        __syncthreads();
    }
    if (tid == 0) g_part[blockIdx.x] = sm[0];
}

// ---------------- phase B: exclusive scan of 196 partials (1 block) ----------------
__global__ void scanB_kernel() {
    __shared__ int sm[256];
    const int tid = threadIdx.x;
    int v = (tid < NBLK_SCAN) ? g_part[tid] : 0;
    sm[tid] = v;
    __syncthreads();
    #pragma unroll
    for (int off = 1; off < 256; off <<= 1) {
        int t = (tid >= off) ? sm[tid - off] : 0;
        __syncthreads();
        sm[tid] += t;
        __syncthreads();
    }
    if (tid < NBLK_SCAN) g_part[tid] = sm[tid] - v;   // exclusive
    if (tid == 0) g_off[NN] = EE;                     // total degree is edge count
}

// ---------------- phase C: in-block scan + base -> g_off / g_cur ----------------
__global__ void scanC_kernel() {
    __shared__ int sm[256];
    const int tid = threadIdx.x;
    const int i = blockIdx.x * 256 + tid;
    int d = (i < NN) ? g_deg[i] : 0;
    sm[tid] = d;
    __syncthreads();
    #pragma unroll
    for (int off = 1; off < 256; off <<= 1) {
        int t = (tid >= off) ? sm[tid - off] : 0;
        __syncthreads();
        sm[tid] += t;
        __syncthreads();
    }
    if (i < NN) {
        int o = g_part[blockIdx.x] + sm[tid] - d;     // exclusive prefix
        g_off[i] = o;
        g_cur[i] = o;
    }
}

__global__ void fill_kernel(const int* __restrict__ row, const int* __restrict__ col) {
    int base = (blockIdx.x * blockDim.x + threadIdx.x) * 2;
    if (base + 1 < EE) {
        int2 r = *(const int2*)&row[base];
        int2 c = *(const int2*)&col[base];
        float dr0 = g_dinv[r.x], dc0 = g_dinv[c.x];
        float dr1 = g_dinv[r.y], dc1 = g_dinv[c.y];
        int p0 = atomicAdd(&g_cur[c.x], 1);
        int p1 = atomicAdd(&g_cur[c.y], 1);
        g_edge[p0] = make_int2(r.x, __float_as_int(dr0 * dc0));
        g_edge[p1] = make_int2(r.y, __float_as_int(dr1 * dc1));
    } else if (base < EE) {
        int r0 = row[base], c0 = col[base];
        int p0 = atomicAdd(&g_cur[c0], 1);
        g_edge[p0] = make_int2(r0, __float_as_int(g_dinv[r0] * g_dinv[c0]));
    }
}

// ---------------- GEMM1: C[N,128] = X[N,128] @ W[128,128], +b1 on cols 64..127 ----
__global__ void __launch_bounds__(256)
gemm128_kernel(const float* __restrict__ X, const float* __restrict__ W,
               const float* __restrict__ bias64, float* __restrict__ C, int nrows) {
    __shared__ float xs[16][132];
    __shared__ float ws[16][128];

    const int tid = threadIdx.x;
    const int tx  = tid & 15;
    const int ty  = tid >> 4;
    const int n0  = blockIdx.x * 128;

    u64 acc[8][4] = {};

    for (int f0 = 0; f0 < 128; f0 += 16) {
        #pragma unroll
        for (int l = 0; l < 2; ++l) {
            int idx = tid + l * 256;
            int m = idx >> 2, fq = idx & 3;
            float4 v = make_float4(0.f, 0.f, 0.f, 0.f);
            if (n0 + m < nrows)
                v = *(const float4*)&X[(size_t)(n0 + m) * 128 + f0 + fq * 4];
            xs[fq * 4 + 0][m] = v.x;
            xs[fq * 4 + 1][m] = v.y;
            xs[fq * 4 + 2][m] = v.z;
            xs[fq * 4 + 3][m] = v.w;
        }
        #pragma unroll
        for (int l = 0; l < 2; ++l) {
            int idx = tid + l * 256;
            int f = idx >> 5, j4 = idx & 31;
            *(float4*)&ws[f][j4 * 4] = *(const float4*)&W[(size_t)(f0 + f) * 128 + j4 * 4];
        }
        __syncthreads();
        #pragma unroll
        for (int f = 0; f < 16; ++f) {
            float4 xa = *(const float4*)&xs[f][ty * 8];
            float4 xb = *(const float4*)&xs[f][ty * 8 + 4];
            const u64* wp = (const u64*)&ws[f][tx * 8];
            u64 w0 = wp[0], w1 = wp[1], w2 = wp[2], w3 = wp[3];
            u64 xr;
            xr = pack2(xa.x, xa.x);
            ffma2(acc[0][0], xr, w0); ffma2(acc[0][1], xr, w1);
            ffma2(acc[0][2], xr, w2); ffma2(acc[0][3], xr, w3);
            xr = pack2(xa.y, xa.y);
            ffma2(acc[1][0], xr, w0); ffma2(acc[1][1], xr, w1);
            ffma2(acc[1][2], xr, w2); ffma2(acc[1][3], xr, w3);
            xr = pack2(xa.z, xa.z);
            ffma2(acc[2][0], xr, w0); ffma2(acc[2][1], xr, w1);
            ffma2(acc[2][2], xr, w2); ffma2(acc[2][3], xr, w3);
            xr = pack2(xa.w, xa.w);
            ffma2(acc[3][0], xr, w0); ffma2(acc[3][1], xr, w1);
            ffma2(acc[3][2], xr, w2); ffma2(acc[3][3], xr, w3);
            xr = pack2(xb.x, xb.x);
            ffma2(acc[4][0], xr, w0); ffma2(acc[4][1], xr, w1);
            ffma2(acc[4][2], xr, w2); ffma2(acc[4][3], xr, w3);
            xr = pack2(xb.y, xb.y);
            ffma2(acc[5][0], xr, w0); ffma2(acc[5][1], xr, w1);
            ffma2(acc[5][2], xr, w2); ffma2(acc[5][3], xr, w3);
            xr = pack2(xb.z, xb.z);
            ffma2(acc[6][0], xr, w0); ffma2(acc[6][1], xr, w1);
            ffma2(acc[6][2], xr, w2); ffma2(acc[6][3], xr, w3);
            xr = pack2(xb.w, xb.w);
            ffma2(acc[7][0], xr, w0); ffma2(acc[7][1], xr, w1);
            ffma2(acc[7][2], xr, w2); ffma2(acc[7][3], xr, w3);
        }
        __syncthreads();
    }

    const int jb = tx * 8;
    float bv[8];
    #pragma unroll
    for (int c = 0; c < 8; ++c) {
        int j = jb + c;
        bv[c] = (j >= 64) ? bias64[j - 64] : 0.0f;
    }
    #pragma unroll
    for (int r = 0; r < 8; ++r) {
        int n = n0 + ty * 8 + r;
        if (n >= nrows) continue;
        float2 p0 = unpack2(acc[r][0]);
        float2 p1 = unpack2(acc[r][1]);
        float2 p2 = unpack2(acc[r][2]);
        float2 p3 = unpack2(acc[r][3]);
        *(float4*)&C[(size_t)n * 128 + jb] =
            make_float4(p0.x + bv[0], p0.y + bv[1], p1.x + bv[2], p1.y + bv[3]);
        *(float4*)&C[(size_t)n * 128 + jb + 4] =
            make_float4(p2.x + bv[4], p2.y + bv[5], p3.x + bv[6], p3.y + bv[7]);
    }
}

// ---------------- prop64: B = relu(A(init) + root')  [vectorized gather] ----
__global__ void prop64_kernel(const float* __restrict__ src,   // A, ld 128, cols 0..63
                              const float* __restrict__ root,  // A+64, ld 128
                              float* __restrict__ out) {       // B, ld 64
    const int gwarp = (blockIdx.x * blockDim.x + threadIdx.x) >> 5;
    const int lane  = threadIdx.x & 31;
    if (gwarp >= NN) return;
    const int n   = gwarp;
    const int beg = g_off[n];
    const int end = g_off[n + 1];
    const int eg = lane >> 4, cg = lane & 15;

    float4 acc = make_float4(0.f, 0.f, 0.f, 0.f);
    int e = beg;
    for (; e + 4 <= end; e += 4) {
        int2 ea = g_edge[e + eg];
        int2 eb = g_edge[e + 2 + eg];
        float4 va = ((const float4*)(src + (size_t)ea.x * 128))[cg];
        float4 vb = ((const float4*)(src + (size_t)eb.x * 128))[cg];
        float wa = __int_as_float(ea.y), wb = __int_as_float(eb.y);
        acc.x = fmaf(wa, va.x, acc.x); acc.y = fmaf(wa, va.y, acc.y);
        acc.z = fmaf(wa, va.z, acc.z); acc.w = fmaf(wa, va.w, acc.w);
        acc.x = fmaf(wb, vb.x, acc.x); acc.y = fmaf(wb, vb.y, acc.y);
        acc.z = fmaf(wb, vb.z, acc.z); acc.w = fmaf(wb, vb.w, acc.w);
    }
    for (; e < end; e += 2) {
        int2 ea = (e + eg < end) ? g_edge[e + eg] : make_int2(0, 0);
        float4 va = ((const float4*)(src + (size_t)ea.x * 128))[cg];
        float wa = __int_as_float(ea.y);
        acc.x = fmaf(wa, va.x, acc.x); acc.y = fmaf(wa, va.y, acc.y);
        acc.z = fmaf(wa, va.z, acc.z); acc.w = fmaf(wa, va.w, acc.w);
    }
    acc.x += __shfl_xor_sync(0xffffffffu, acc.x, 16);
    acc.y += __shfl_xor_sync(0xffffffffu, acc.y, 16);
    acc.z += __shfl_xor_sync(0xffffffffu, acc.z, 16);
    acc.w += __shfl_xor_sync(0xffffffffu, acc.w, 16);

    if (lane < 16) {
        float4 rp = ((const float4*)(root + (size_t)n * 128))[cg];
        float4 y = make_float4(fmaxf(acc.x + rp.x, 0.f), fmaxf(acc.y + rp.y, 0.f),
                               fmaxf(acc.z + rp.z, 0.f), fmaxf(acc.w + rp.w, 0.f));
        ((float4*)(out + (size_t)n * 64))[cg] = y;
    }
}

// ---------------- prop64f: H = 0.5*sum_k relu(A(B)_k @ Wd_k + root_k) ----
__global__ void __launch_bounds__(256)
prop64f_kernel(const float* __restrict__ src,      // B, ld 64
               const float* __restrict__ root,     // A+64, ld 128 (includes b1)
               const float* __restrict__ w1d,      // [2][32][32]
               float* __restrict__ out) {          // H3, ld 128, cols 0..31
    __shared__ float wd[2][32][32];
    __shared__ float sm[8][64];
    const int tid = threadIdx.x;
    #pragma unroll
    for (int l = 0; l < 8; ++l)
        ((float*)wd)[tid + l * 256] = w1d[tid + l * 256];
    __syncthreads();

    const int gwarp = (blockIdx.x * blockDim.x + tid) >> 5;
    const int lane  = tid & 31;
    const int wwarp = tid >> 5;
    if (gwarp >= NN) return;
    const int n   = gwarp;
    const int beg = g_off[n];
    const int end = g_off[n + 1];
    const int eg = lane >> 4, cg = lane & 15;

    float4 acc = make_float4(0.f, 0.f, 0.f, 0.f);
    int e = beg;
    for (; e + 4 <= end; e += 4) {
        int2 ea = g_edge[e + eg];
        int2 eb = g_edge[e + 2 + eg];
        float4 va = ((const float4*)(src + (size_t)ea.x * 64))[cg];
        float4 vb = ((const float4*)(src + (size_t)eb.x * 64))[cg];
        float wa = __int_as_float(ea.y), wb = __int_as_float(eb.y);
        acc.x = fmaf(wa, va.x, acc.x); acc.y = fmaf(wa, va.y, acc.y);
        acc.z = fmaf(wa, va.z, acc.z); acc.w = fmaf(wa, va.w, acc.w);
        acc.x = fmaf(wb, vb.x, acc.x); acc.y = fmaf(wb, vb.y, acc.y);
        acc.z = fmaf(wb, vb.z, acc.z); acc.w = fmaf(wb, vb.w, acc.w);
    }
    for (; e < end; e += 2) {
        int2 ea = (e + eg < end) ? g_edge[e + eg] : make_int2(0, 0);
        float4 va = ((const float4*)(src + (size_t)ea.x * 64))[cg];
        float wa = __int_as_float(ea.y);
        acc.x = fmaf(wa, va.x, acc.x); acc.y = fmaf(wa, va.y, acc.y);
        acc.z = fmaf(wa, va.z, acc.z); acc.w = fmaf(wa, va.w, acc.w);
    }
    acc.x += __shfl_xor_sync(0xffffffffu, acc.x, 16);
    acc.y += __shfl_xor_sync(0xffffffffu, acc.y, 16);
    acc.z += __shfl_xor_sync(0xffffffffu, acc.z, 16);
    acc.w += __shfl_xor_sync(0xffffffffu, acc.w, 16);

    if (lane < 16) ((float4*)sm[wwarp])[cg] = acc;
    __syncwarp();
    float a0 = sm[wwarp][lane];
    float a1 = sm[wwarp][lane + 32];

    float z0 = 0.f, z1 = 0.f;
    #pragma unroll
    for (int l = 0; l < 32; ++l) {
        float b0  = __shfl_sync(0xffffffffu, a0, l);
        float b1v = __shfl_sync(0xffffffffu, a1, l);
        z0 = fmaf(b0,  wd[0][l][lane], z0);
        z1 = fmaf(b1v, wd[1][l][lane], z1);
    }

    const float* rp = root + (size_t)n * 128;
    float y0 = fmaxf(z0 + rp[lane],      0.f);
    float y1 = fmaxf(z1 + rp[lane + 32], 0.f);
    out[(size_t)n * 128 + lane] = 0.5f * (y0 + y1);
}

// ---------------- prop32: vectorized width-32 gather within H3 (ld 128) ----
template <int SOFF, int DOFF, bool WITH_S>
__global__ void prop32_kernel(float* __restrict__ buf) {
    const int gwarp = (blockIdx.x * blockDim.x + threadIdx.x) >> 5;
    const int lane  = threadIdx.x & 31;
    if (gwarp >= NN) return;
    const int n   = gwarp;
    const int beg = g_off[n];
    const int end = g_off[n + 1];
    const int eg = lane >> 3, cg = lane & 7;
    const float* src = buf + SOFF;

    float4 acc = make_float4(0.f, 0.f, 0.f, 0.f);
    float sw = 0.f;
    int e = beg;
    for (; e + 8 <= end; e += 8) {
        int2 ea = g_edge[e + eg];
        int2 eb = g_edge[e + 4 + eg];
        float4 va = ((const float4*)(src + (size_t)ea.x * 128))[cg];
        float4 vb = ((const float4*)(src + (size_t)eb.x * 128))[cg];
        float wa = __int_as_float(ea.y), wb = __int_as_float(eb.y);
        acc.x = fmaf(wa, va.x, acc.x); acc.y = fmaf(wa, va.y, acc.y);
        acc.z = fmaf(wa, va.z, acc.z); acc.w = fmaf(wa, va.w, acc.w);
        acc.x = fmaf(wb, vb.x, acc.x); acc.y = fmaf(wb, vb.y, acc.y);
        acc.z = fmaf(wb, vb.z, acc.z); acc.w = fmaf(wb, vb.w, acc.w);
        if (WITH_S) sw += wa + wb;
    }
    for (; e < end; e += 4) {
        int2 ea = (e + eg < end) ? g_edge[e + eg] : make_int2(0, 0);
        float4 va = ((const float4*)(src + (size_t)ea.x * 128))[cg];
        float wa = __int_as_float(ea.y);
        acc.x = fmaf(wa, va.x, acc.x); acc.y = fmaf(wa, va.y, acc.y);
        acc.z = fmaf(wa, va.z, acc.z); acc.w = fmaf(wa, va.w, acc.w);
        if (WITH_S) sw += wa;
    }
    #pragma unroll
    for (int o = 8; o <= 16; o <<= 1) {
        acc.x += __shfl_xor_sync(0xffffffffu, acc.x, o);
        acc.y += __shfl_xor_sync(0xffffffffu, acc.y, o);
        acc.z += __shfl_xor_sync(0xffffffffu, acc.z, o);
        acc.w += __shfl_xor_sync(0xffffffffu, acc.w, o);
        if (WITH_S) sw += __shfl_xor_sync(0xffffffffu, sw, o);
    }
    if (lane < 8)
        ((float4*)(buf + (size_t)n * 128 + DOFF))[cg] = acc;
    if (WITH_S && lane == 0) g_s[n] = sw;
}

// ---------------- gemm96 + fused log_softmax ----------------
__global__ void __launch_bounds__(256)
gemm96lsm_kernel(const float* __restrict__ X,       // H3, ld 128 (cols 0..95)
                 const float* __restrict__ W,       // 96 x 40
                 float* __restrict__ out, int nrows) {
    __shared__ float xs[16][132];
    __shared__ float ws[16][40];
    __shared__ float sbG[40], sbR[40];

    const int tid = threadIdx.x;
    const int tx  = tid & 7;
    const int ty  = tid >> 3;
    const int n0  = blockIdx.x * 128;

    if (tid < 40) { sbG[tid] = g_bG[tid]; sbR[tid] = g_bR[tid]; }

    float acc[4][5] = {};

    for (int f0 = 0; f0 < 96; f0 += 16) {
        #pragma unroll
        for (int l = 0; l < 2; ++l) {
            int idx = tid + l * 256;
            int m = idx >> 2, fq = idx & 3;
            float4 v = make_float4(0.f, 0.f, 0.f, 0.f);
            if (n0 + m < nrows)
                v = *(const float4*)&X[(size_t)(n0 + m) * 128 + f0 + fq * 4];
            xs[fq * 4 + 0][m] = v.x;
            xs[fq * 4 + 1][m] = v.y;
            xs[fq * 4 + 2][m] = v.z;
            xs[fq * 4 + 3][m] = v.w;
        }
        #pragma unroll
        for (int l = 0; l < 3; ++l) {
            int idx = tid + l * 256;
            if (idx < 640) {
                int f = idx / 40, j = idx - f * 40;
                ws[f][j] = W[(size_t)(f0 + f) * 40 + j];
            }
        }
        __syncthreads();
        #pragma unroll
        for (int f = 0; f < 16; ++f) {
            float w[5];
            #pragma unroll
            for (int c = 0; c < 5; ++c) w[c] = ws[f][tx * 5 + c];
            #pragma unroll
            for (int r = 0; r < 4; ++r) {
                float xv = xs[f][ty * 4 + r];
                #pragma unroll
                for (int c = 0; c < 5; ++c) acc[r][c] = fmaf(xv, w[c], acc[r][c]);
            }
        }
        __syncthreads();
    }

    #pragma unroll
    for (int r = 0; r < 4; ++r) {
        int n = n0 + ty * 4 + r;
        float sv = (n < nrows) ? g_s[n] : 0.f;
        float y[5];
        #pragma unroll
        for (int c = 0; c < 5; ++c) {
            int j = tx * 5 + c;
            y[c] = acc[r][c] + sv * sbG[j] + sbR[j];
        }
        float m = y[0];
        #pragma unroll
        for (int c = 1; c < 5; ++c) m = fmaxf(m, y[c]);
        #pragma unroll
        for (int o = 1; o < 8; o <<= 1) m = fmaxf(m, __shfl_xor_sync(0xffffffffu, m, o));
        float s = 0.f;
        #pragma unroll
        for (int c = 0; c < 5; ++c) s += expf(y[c] - m);
        #pragma unroll
        for (int o = 1; o < 8; o <<= 1) s += __shfl_xor_sync(0xffffffffu, s, o);
        float lse = m + logf(s);
        if (n < nrows) {
            #pragma unroll
            for (int c = 0; c < 5; ++c)
                out[(size_t)n * 40 + tx * 5 + c] = y[c] - lse;
        }
    }
}

// ---------------- launch ----------------
extern "C" void kernel_launch(void* const* d_in, const int* in_sizes, int n_in,
                              void* d_out, int out_size) {
    const float* x    = (const float*)d_in[0];
    const int*   eidx = (const int*)  d_in[1];
    const float* w1i  = (const float*)d_in[2];
    const float* w1d  = (const float*)d_in[3];
    const float* w1r  = (const float*)d_in[4];
    const float* b1   = (const float*)d_in[5];
    const float* w2i  = (const float*)d_in[6];
    const float* w2d  = (const float*)d_in[7];
    const float* w2r  = (const float*)d_in[8];
    const float* b2   = (const float*)d_in[9];
    float* outp = (float*)d_out;

    const int* row = eidx;
    const int* col = eidx + EE;

    float *A, *B, *H3, *Wp1, *W3;
    cudaGetSymbolAddress((void**)&A,   g_A);
    cudaGetSymbolAddress((void**)&B,   g_B);
    cudaGetSymbolAddress((void**)&H3,  g_H3);
    cudaGetSymbolAddress((void**)&Wp1, g_Wp1);
    cudaGetSymbolAddress((void**)&W3,  g_W3);

    static cudaStream_t s2 = nullptr;
    static cudaEvent_t  evFork = nullptr, evJoin = nullptr;
    if (s2 == nullptr) {
        cudaStreamCreateWithFlags(&s2, cudaStreamNonBlocking);
        cudaEventCreateWithFlags(&evFork, cudaEventDisableTiming);
        cudaEventCreateWithFlags(&evJoin, cudaEventDisableTiming);
    }

    const int TB = 256;
    const int nblkE2 = (EE / 2 + TB - 1) / TB;         // 1563
    const int nblkW  = (NN * 32 + TB - 1) / TB;        // 6250 (warp per node)
    const int gR = (NN + 127) / 128;                   // 391 row tiles

    // init (zero deg + all weight folding) on main, then fork gemm128 to s2
    init_kernel<<<(NN + TB - 1) / TB, TB>>>(w1i, w1r, w2i, w2d, w2r, b2);
    cudaEventRecord(evFork, 0);
    cudaStreamWaitEvent(s2, evFork, 0);
    gemm128_kernel<<<gR, TB, 0, s2>>>(x, Wp1, b1, A, NN);
    cudaEventRecord(evJoin, s2);

    hist_kernel<<<nblkE2, TB>>>(col);
    scanA_kernel<<<NBLK_SCAN, 256>>>();
    scanB_kernel<<<1, 256>>>();
    scanC_kernel<<<NBLK_SCAN, 256>>>();
    fill_kernel<<<nblkE2, TB>>>(row, col);

    cudaStreamWaitEvent(0, evJoin, 0);

    // ---- conv1 ----
    prop64_kernel<<<nblkW, TB>>>(A, A + 64, B);
    prop64f_kernel<<<nblkW, TB>>>(B, A + 64, w1d, H3);       // H -> H3 cols 0..31

    // ---- conv2 (fully folded) ----
    prop32_kernel<0, 32, true ><<<nblkW, TB>>>(H3);          // PH  = A(H),  + s[n]
    prop32_kernel<32, 64, false><<<nblkW, TB>>>(H3);         // PPH = A(PH)
    gemm96lsm_kernel<<<gR, TB>>>(H3, W3, outp, NN);
}

// round 9
// speedup vs baseline: 1.6339x; 1.0107x over previous
#include <cuda_runtime.h>
#include <math.h>

#define NN 50000
#define EE 800000
#define NBLK_SCAN 196            // ceil(50000/256)

typedef unsigned long long u64;

// ---------------- f32x2 packed-FMA helpers (bit-identical fp32) ----------------
__device__ __forceinline__ u64 pack2(float lo, float hi) {
    u64 r; asm("mov.b64 %0, {%1, %2};" : "=l"(r) : "f"(lo), "f"(hi)); return r;
}
__device__ __forceinline__ void ffma2(u64& d, u64 a, u64 b) {
    asm("fma.rn.f32x2 %0, %1, %2, %0;" : "+l"(d) : "l"(a), "l"(b));
}
__device__ __forceinline__ float2 unpack2(u64 v) {
    float2 f; asm("mov.b64 {%0, %1}, %2;" : "=f"(f.x), "=f"(f.y) : "l"(v)); return f;
}

// ---------------- scratch (device globals, no runtime alloc) ----------------
__device__ int   g_deg[NN];
__device__ int   g_off[NN + 1];
__device__ int   g_cur[NN];
__device__ float g_dinv[NN];
__device__ int   g_part[NBLK_SCAN];
__device__ int2  g_edge[EE];              // {src, __float_as_int(ew)}
__device__ float g_s[NN];                 // s[n] = sum of ew into n

__device__ float g_A [(size_t)NN * 128];  // conv1: [init(64) | root+b1(64)]
__device__ float g_B [(size_t)NN * 64];   // conv1 after t=0
__device__ float g_H3[(size_t)NN * 128];  // [H(0:32) | PH(32:64) | PPH(64:96) | pad]

__device__ float g_Wp1[128 * 128];        // packed [w1_init | w1_root]
__device__ float g_W3 [96 * 40];          // folded conv2 weights [WR; Wb; Wa]
__device__ float g_bG [40];               // constant-through-A bias
__device__ float g_bR [40];               // direct bias

// ---------------- init: zero degree + pack Wp1 + fold conv2 weights ----------------
__global__ void init_kernel(const float* __restrict__ w1i, const float* __restrict__ w1r,
                            const float* __restrict__ w2i, const float* __restrict__ w2d,
                            const float* __restrict__ w2r, const float* __restrict__ b2) {
    int i = blockIdx.x * blockDim.x + threadIdx.x;
    if (i < NN) g_deg[i] = 0;
    if (i < 16384) {                       // Wp1 : 128 x 128 = [w1_init | w1_root]
        int f = i >> 7, j = i & 127;
        float v;
        if (j < 64) { int k = j >> 5, h = j & 31; v = w1i[(k * 128 + f) * 32 + h]; }
        else        { int j2 = j - 64; int k = j2 >> 5, h = j2 & 31; v = w1r[(k * 128 + f) * 32 + h]; }
        g_Wp1[i] = v;
    } else if (i < 16384 + 96 * 40) {      // W3' : 96 x 40
        int i2 = i - 16384;
        int f = i2 / 40, g = i2 % 40;
        float v = 0.0f;
        if (f < 32) {
            v = 0.5f * (w2r[f * 40 + g] + w2r[(32 + f) * 40 + g]);
        } else if (f < 64) {
            int fr = f - 32;
            #pragma unroll
            for (int k = 0; k < 2; ++k) {
                float s = 0.0f;
                for (int j = 0; j < 40; ++j)
                    s = fmaf(w2r[(k * 32 + fr) * 40 + j], w2d[(k * 40 + j) * 40 + g], s);
                v += s;
            }
            v *= 0.5f;
        } else {
            int fr = f - 64;
            #pragma unroll
            for (int k = 0; k < 2; ++k) {
                float s = 0.0f;
                for (int j = 0; j < 40; ++j)
                    s = fmaf(w2i[(k * 32 + fr) * 40 + j], w2d[(k * 40 + j) * 40 + g], s);
                v += s;
            }
            v *= 0.5f;
        }
        g_W3[i2] = v;
    } else if (i < 16384 + 96 * 40 + 80) {
        int g = i - (16384 + 96 * 40);
        if (g < 40) {
            float v = 0.0f;
            #pragma unroll
            for (int k = 0; k < 2; ++k)
                for (int j = 0; j < 40; ++j)
                    v = fmaf(b2[k * 40 + j], w2d[(k * 40 + j) * 40 + g], v);
            g_bG[g] = 0.5f * v;
        } else {
            int gg = g - 40;
            g_bR[gg] = 0.5f * (b2[gg] + b2[40 + gg]);
        }
    }
}

// ---------------- hist: 4 edges per thread (int4) ----------------
__global__ void hist_kernel(const int* __restrict__ col) {
    int i = (blockIdx.x * blockDim.x + threadIdx.x) * 4;
    if (i + 4 <= EE) {
        int4 c = *(const int4*)&col[i];
        atomicAdd(&g_deg[c.x], 1);
        atomicAdd(&g_deg[c.y], 1);
        atomicAdd(&g_deg[c.z], 1);
        atomicAdd(&g_deg[c.w], 1);
    } else {
        for (; i < EE; ++i) atomicAdd(&g_deg[col[i]], 1);
    }
}

// ---------------- scan phase A: block-reduce degrees + dinv ----------------
__global__ void scanA_kernel() {
    __shared__ int sm[256];
    const int tid = threadIdx.x;
    const int i = blockIdx.x * 256 + tid;
    int d = (i < NN) ? g_deg[i] : 0;
    if (i < NN) g_dinv[i] = (d > 0) ? rsqrtf((float)d) : 0.0f;
    sm[tid] = d;
    __syncthreads();
    #pragma unroll
    for (int off = 128; off > 0; off >>= 1) {
        if (tid < off) sm[tid] += sm[tid + off];
        __syncthreads();
    }
    if (tid == 0) g_part[blockIdx.x] = sm[0];
    if (blockIdx.x == 0 && tid == 0) g_off[NN] = EE;
}

// ---------------- scan phase C: base from partials + in-block scan ----------------
__global__ void scanC_kernel() {
    __shared__ int sm[256];
    const int tid = threadIdx.x;
    const int i = blockIdx.x * 256 + tid;

    // reduce partials < blockIdx.x
    int p = (tid < blockIdx.x) ? g_part[tid] : 0;    // blockIdx.x <= 195 < 256
    sm[tid] = p;
    __syncthreads();
    #pragma unroll
    for (int off = 128; off > 0; off >>= 1) {
        if (tid < off) sm[tid] += sm[tid + off];
        __syncthreads();
    }
    int base = sm[0];
    __syncthreads();

    // in-block inclusive scan of degrees
    int d = (i < NN) ? g_deg[i] : 0;
    sm[tid] = d;
    __syncthreads();
    #pragma unroll
    for (int off = 1; off < 256; off <<= 1) {
        int t = (tid >= off) ? sm[tid - off] : 0;
        __syncthreads();
        sm[tid] += t;
        __syncthreads();
    }
    if (i < NN) {
        int o = base + sm[tid] - d;                  // exclusive prefix
        g_off[i] = o;
        g_cur[i] = o;
    }
}

// ---------------- fill: 4 edges per thread (int4) ----------------
__global__ void fill_kernel(const int* __restrict__ row, const int* __restrict__ col) {
    int base = (blockIdx.x * blockDim.x + threadIdx.x) * 4;
    if (base + 4 <= EE) {
        int4 r = *(const int4*)&row[base];
        int4 c = *(const int4*)&col[base];
        float w0 = g_dinv[r.x] * g_dinv[c.x];
        float w1 = g_dinv[r.y] * g_dinv[c.y];
        float w2 = g_dinv[r.z] * g_dinv[c.z];
        float w3 = g_dinv[r.w] * g_dinv[c.w];
        int p0 = atomicAdd(&g_cur[c.x], 1);
        int p1 = atomicAdd(&g_cur[c.y], 1);
        int p2 = atomicAdd(&g_cur[c.z], 1);
        int p3 = atomicAdd(&g_cur[c.w], 1);
        g_edge[p0] = make_int2(r.x, __float_as_int(w0));
        g_edge[p1] = make_int2(r.y, __float_as_int(w1));
        g_edge[p2] = make_int2(r.z, __float_as_int(w2));
        g_edge[p3] = make_int2(r.w, __float_as_int(w3));
    } else {
        for (; base < EE; ++base) {
            int r0 = row[base], c0 = col[base];
            int p0 = atomicAdd(&g_cur[c0], 1);
            g_edge[p0] = make_int2(r0, __float_as_int(g_dinv[r0] * g_dinv[c0]));
        }
    }
}

// ---------------- GEMM1: C[N,128] = X[N,128] @ W[128,128], +b1 on cols 64..127 ----
__global__ void __launch_bounds__(256)
gemm128_kernel(const float* __restrict__ X, const float* __restrict__ W,
               const float* __restrict__ bias64, float* __restrict__ C, int nrows) {
    __shared__ float xs[16][132];
    __shared__ float ws[16][128];

    const int tid = threadIdx.x;
    const int tx  = tid & 15;
    const int ty  = tid >> 4;
    const int n0  = blockIdx.x * 128;

    u64 acc[8][4] = {};

    for (int f0 = 0; f0 < 128; f0 += 16) {
        #pragma unroll
        for (int l = 0; l < 2; ++l) {
            int idx = tid + l * 256;
            int m = idx >> 2, fq = idx & 3;
            float4 v = make_float4(0.f, 0.f, 0.f, 0.f);
            if (n0 + m < nrows)
                v = *(const float4*)&X[(size_t)(n0 + m) * 128 + f0 + fq * 4];
            xs[fq * 4 + 0][m] = v.x;
            xs[fq * 4 + 1][m] = v.y;
            xs[fq * 4 + 2][m] = v.z;
            xs[fq * 4 + 3][m] = v.w;
        }
        #pragma unroll
        for (int l = 0; l < 2; ++l) {
            int idx = tid + l * 256;
            int f = idx >> 5, j4 = idx & 31;
            *(float4*)&ws[f][j4 * 4] = *(const float4*)&W[(size_t)(f0 + f) * 128 + j4 * 4];
        }
        __syncthreads();
        #pragma unroll
        for (int f = 0; f < 16; ++f) {
            float4 xa = *(const float4*)&xs[f][ty * 8];
            float4 xb = *(const float4*)&xs[f][ty * 8 + 4];
            const u64* wp = (const u64*)&ws[f][tx * 8];
            u64 w0 = wp[0], w1 = wp[1], w2 = wp[2], w3 = wp[3];
            u64 xr;
            xr = pack2(xa.x, xa.x);
            ffma2(acc[0][0], xr, w0); ffma2(acc[0][1], xr, w1);
            ffma2(acc[0][2], xr, w2); ffma2(acc[0][3], xr, w3);
            xr = pack2(xa.y, xa.y);
            ffma2(acc[1][0], xr, w0); ffma2(acc[1][1], xr, w1);
            ffma2(acc[1][2], xr, w2); ffma2(acc[1][3], xr, w3);
            xr = pack2(xa.z, xa.z);
            ffma2(acc[2][0], xr, w0); ffma2(acc[2][1], xr, w1);
            ffma2(acc[2][2], xr, w2); ffma2(acc[2][3], xr, w3);
            xr = pack2(xa.w, xa.w);
            ffma2(acc[3][0], xr, w0); ffma2(acc[3][1], xr, w1);
            ffma2(acc[3][2], xr, w2); ffma2(acc[3][3], xr, w3);
            xr = pack2(xb.x, xb.x);
            ffma2(acc[4][0], xr, w0); ffma2(acc[4][1], xr, w1);
            ffma2(acc[4][2], xr, w2); ffma2(acc[4][3], xr, w3);
            xr = pack2(xb.y, xb.y);
            ffma2(acc[5][0], xr, w0); ffma2(acc[5][1], xr, w1);
            ffma2(acc[5][2], xr, w2); ffma2(acc[5][3], xr, w3);
            xr = pack2(xb.z, xb.z);
            ffma2(acc[6][0], xr, w0); ffma2(acc[6][1], xr, w1);
            ffma2(acc[6][2], xr, w2); ffma2(acc[6][3], xr, w3);
            xr = pack2(xb.w, xb.w);
            ffma2(acc[7][0], xr, w0); ffma2(acc[7][1], xr, w1);
            ffma2(acc[7][2], xr, w2); ffma2(acc[7][3], xr, w3);
        }
        __syncthreads();
    }

    const int jb = tx * 8;
    float bv[8];
    #pragma unroll
    for (int c = 0; c < 8; ++c) {
        int j = jb + c;
        bv[c] = (j >= 64) ? bias64[j - 64] : 0.0f;
    }
    #pragma unroll
    for (int r = 0; r < 8; ++r) {
        int n = n0 + ty * 8 + r;
        if (n >= nrows) continue;
        float2 p0 = unpack2(acc[r][0]);
        float2 p1 = unpack2(acc[r][1]);
        float2 p2 = unpack2(acc[r][2]);
        float2 p3 = unpack2(acc[r][3]);
        *(float4*)&C[(size_t)n * 128 + jb] =
            make_float4(p0.x + bv[0], p0.y + bv[1], p1.x + bv[2], p1.y + bv[3]);
        *(float4*)&C[(size_t)n * 128 + jb + 4] =
            make_float4(p2.x + bv[4], p2.y + bv[5], p3.x + bv[6], p3.y + bv[7]);
    }
}

// ---------------- prop64: B = relu(A(init) + root')  [8-edge iters, MLP 4] ----
__global__ void prop64_kernel(const float* __restrict__ src,   // A, ld 128, cols 0..63
                              const float* __restrict__ root,  // A+64, ld 128
                              float* __restrict__ out) {       // B, ld 64
    const int gwarp = (blockIdx.x * blockDim.x + threadIdx.x) >> 5;
    const int lane  = threadIdx.x & 31;
    if (gwarp >= NN) return;
    const int n   = gwarp;
    const int beg = g_off[n];
    const int end = g_off[n + 1];
    const int eg = lane >> 4, cg = lane & 15;

    float4 acc = make_float4(0.f, 0.f, 0.f, 0.f);
    int e = beg;
    for (; e + 8 <= end; e += 8) {
        int2 e0 = g_edge[e + eg];
        int2 e1 = g_edge[e + 2 + eg];
        int2 e2 = g_edge[e + 4 + eg];
        int2 e3 = g_edge[e + 6 + eg];
        float4 v0 = ((const float4*)(src + (size_t)e0.x * 128))[cg];
        float4 v1 = ((const float4*)(src + (size_t)e1.x * 128))[cg];
        float4 v2 = ((const float4*)(src + (size_t)e2.x * 128))[cg];
        float4 v3 = ((const float4*)(src + (size_t)e3.x * 128))[cg];
        float w0 = __int_as_float(e0.y), w1 = __int_as_float(e1.y);
        float w2 = __int_as_float(e2.y), w3 = __int_as_float(e3.y);
        acc.x = fmaf(w0, v0.x, acc.x); acc.y = fmaf(w0, v0.y, acc.y);
        acc.z = fmaf(w0, v0.z, acc.z); acc.w = fmaf(w0, v0.w, acc.w);
        acc.x = fmaf(w1, v1.x, acc.x); acc.y = fmaf(w1, v1.y, acc.y);
        acc.z = fmaf(w1, v1.z, acc.z); acc.w = fmaf(w1, v1.w, acc.w);
        acc.x = fmaf(w2, v2.x, acc.x); acc.y = fmaf(w2, v2.y, acc.y);
        acc.z = fmaf(w2, v2.z, acc.z); acc.w = fmaf(w2, v2.w, acc.w);
        acc.x = fmaf(w3, v3.x, acc.x); acc.y = fmaf(w3, v3.y, acc.y);
        acc.z = fmaf(w3, v3.z, acc.z); acc.w = fmaf(w3, v3.w, acc.w);
    }
    for (; e < end; e += 2) {
        int2 ea = (e + eg < end) ? g_edge[e + eg] : make_int2(0, 0);
        float4 va = ((const float4*)(src + (size_t)ea.x * 128))[cg];
        float wa = __int_as_float(ea.y);
        acc.x = fmaf(wa, va.x, acc.x); acc.y = fmaf(wa, va.y, acc.y);
        acc.z = fmaf(wa, va.z, acc.z); acc.w = fmaf(wa, va.w, acc.w);
    }
    acc.x += __shfl_xor_sync(0xffffffffu, acc.x, 16);
    acc.y += __shfl_xor_sync(0xffffffffu, acc.y, 16);
    acc.z += __shfl_xor_sync(0xffffffffu, acc.z, 16);
    acc.w += __shfl_xor_sync(0xffffffffu, acc.w, 16);

    if (lane < 16) {
        float4 rp = ((const float4*)(root + (size_t)n * 128))[cg];
        float4 y = make_float4(fmaxf(acc.x + rp.x, 0.f), fmaxf(acc.y + rp.y, 0.f),
                               fmaxf(acc.z + rp.z, 0.f), fmaxf(acc.w + rp.w, 0.f));
        ((float4*)(out + (size_t)n * 64))[cg] = y;
    }
}

// ---------------- prop64f: H = 0.5*sum_k relu(A(B)_k @ Wd_k + root_k) ----
__global__ void __launch_bounds__(256)
prop64f_kernel(const float* __restrict__ src,      // B, ld 64
               const float* __restrict__ root,     // A+64, ld 128 (includes b1)
               const float* __restrict__ w1d,      // [2][32][32]
               float* __restrict__ out) {          // H3, ld 128, cols 0..31
    __shared__ float wd[2][32][32];
    __shared__ float sm[8][64];
    const int tid = threadIdx.x;
    #pragma unroll
    for (int l = 0; l < 8; ++l)
        ((float*)wd)[tid + l * 256] = w1d[tid + l * 256];
    __syncthreads();

    const int gwarp = (blockIdx.x * blockDim.x + tid) >> 5;
    const int lane  = tid & 31;
    const int wwarp = tid >> 5;
    if (gwarp >= NN) return;
    const int n   = gwarp;
    const int beg = g_off[n];
    const int end = g_off[n + 1];
    const int eg = lane >> 4, cg = lane & 15;

    float4 acc = make_float4(0.f, 0.f, 0.f, 0.f);
    int e = beg;
    for (; e + 8 <= end; e += 8) {
        int2 e0 = g_edge[e + eg];
        int2 e1 = g_edge[e + 2 + eg];
        int2 e2 = g_edge[e + 4 + eg];
        int2 e3 = g_edge[e + 6 + eg];
        float4 v0 = ((const float4*)(src + (size_t)e0.x * 64))[cg];
        float4 v1 = ((const float4*)(src + (size_t)e1.x * 64))[cg];
        float4 v2 = ((const float4*)(src + (size_t)e2.x * 64))[cg];
        float4 v3 = ((const float4*)(src + (size_t)e3.x * 64))[cg];
        float w0 = __int_as_float(e0.y), w1 = __int_as_float(e1.y);
        float w2 = __int_as_float(e2.y), w3 = __int_as_float(e3.y);
        acc.x = fmaf(w0, v0.x, acc.x); acc.y = fmaf(w0, v0.y, acc.y);
        acc.z = fmaf(w0, v0.z, acc.z); acc.w = fmaf(w0, v0.w, acc.w);
        acc.x = fmaf(w1, v1.x, acc.x); acc.y = fmaf(w1, v1.y, acc.y);
        acc.z = fmaf(w1, v1.z, acc.z); acc.w = fmaf(w1, v1.w, acc.w);
        acc.x = fmaf(w2, v2.x, acc.x); acc.y = fmaf(w2, v2.y, acc.y);
        acc.z = fmaf(w2, v2.z, acc.z); acc.w = fmaf(w2, v2.w, acc.w);
        acc.x = fmaf(w3, v3.x, acc.x); acc.y = fmaf(w3, v3.y, acc.y);
        acc.z = fmaf(w3, v3.z, acc.z); acc.w = fmaf(w3, v3.w, acc.w);
    }
    for (; e < end; e += 2) {
        int2 ea = (e + eg < end) ? g_edge[e + eg] : make_int2(0, 0);
        float4 va = ((const float4*)(src + (size_t)ea.x * 64))[cg];
        float wa = __int_as_float(ea.y);
        acc.x = fmaf(wa, va.x, acc.x); acc.y = fmaf(wa, va.y, acc.y);
        acc.z = fmaf(wa, va.z, acc.z); acc.w = fmaf(wa, va.w, acc.w);
    }
    acc.x += __shfl_xor_sync(0xffffffffu, acc.x, 16);
    acc.y += __shfl_xor_sync(0xffffffffu, acc.y, 16);
    acc.z += __shfl_xor_sync(0xffffffffu, acc.z, 16);
    acc.w += __shfl_xor_sync(0xffffffffu, acc.w, 16);

    if (lane < 16) ((float4*)sm[wwarp])[cg] = acc;
    __syncwarp();
    float a0 = sm[wwarp][lane];
    float a1 = sm[wwarp][lane + 32];

    float z0 = 0.f, z1 = 0.f;
    #pragma unroll
    for (int l = 0; l < 32; ++l) {
        float b0  = __shfl_sync(0xffffffffu, a0, l);
        float b1v = __shfl_sync(0xffffffffu, a1, l);
        z0 = fmaf(b0,  wd[0][l][lane], z0);
        z1 = fmaf(b1v, wd[1][l][lane], z1);
    }

    const float* rp = root + (size_t)n * 128;
    float y0 = fmaxf(z0 + rp[lane],      0.f);
    float y1 = fmaxf(z1 + rp[lane + 32], 0.f);
    out[(size_t)n * 128 + lane] = 0.5f * (y0 + y1);
}

// ---------------- prop32: width-32 gather, 16-edge iters (MLP 4) ----------------
template <int SOFF, int DOFF, bool WITH_S>
__global__ void prop32_kernel(float* __restrict__ buf) {
    const int gwarp = (blockIdx.x * blockDim.x + threadIdx.x) >> 5;
    const int lane  = threadIdx.x & 31;
    if (gwarp >= NN) return;
    const int n   = gwarp;
    const int beg = g_off[n];
    const int end = g_off[n + 1];
    const int eg = lane >> 3, cg = lane & 7;
    const float* src = buf + SOFF;

    float4 acc = make_float4(0.f, 0.f, 0.f, 0.f);
    float sw = 0.f;
    int e = beg;
    for (; e + 16 <= end; e += 16) {
        int2 e0 = g_edge[e + eg];
        int2 e1 = g_edge[e + 4 + eg];
        int2 e2 = g_edge[e + 8 + eg];
        int2 e3 = g_edge[e + 12 + eg];
        float4 v0 = ((const float4*)(src + (size_t)e0.x * 128))[cg];
        float4 v1 = ((const float4*)(src + (size_t)e1.x * 128))[cg];
        float4 v2 = ((const float4*)(src + (size_t)e2.x * 128))[cg];
        float4 v3 = ((const float4*)(src + (size_t)e3.x * 128))[cg];
        float w0 = __int_as_float(e0.y), w1 = __int_as_float(e1.y);
        float w2 = __int_as_float(e2.y), w3 = __int_as_float(e3.y);
        acc.x = fmaf(w0, v0.x, acc.x); acc.y = fmaf(w0, v0.y, acc.y);
        acc.z = fmaf(w0, v0.z, acc.z); acc.w = fmaf(w0, v0.w, acc.w);
        acc.x = fmaf(w1, v1.x, acc.x); acc.y = fmaf(w1, v1.y, acc.y);
        acc.z = fmaf(w1, v1.z, acc.z); acc.w = fmaf(w1, v1.w, acc.w);
        acc.x = fmaf(w2, v2.x, acc.x); acc.y = fmaf(w2, v2.y, acc.y);
        acc.z = fmaf(w2, v2.z, acc.z); acc.w = fmaf(w2, v2.w, acc.w);
        acc.x = fmaf(w3, v3.x, acc.x); acc.y = fmaf(w3, v3.y, acc.y);
        acc.z = fmaf(w3, v3.z, acc.z); acc.w = fmaf(w3, v3.w, acc.w);
        if (WITH_S) sw += w0 + w1 + w2 + w3;
    }
    for (; e < end; e += 4) {
        int2 ea = (e + eg < end) ? g_edge[e + eg] : make_int2(0, 0);
        float4 va = ((const float4*)(src + (size_t)ea.x * 128))[cg];
        float wa = __int_as_float(ea.y);
        acc.x = fmaf(wa, va.x, acc.x); acc.y = fmaf(wa, va.y, acc.y);
        acc.z = fmaf(wa, va.z, acc.z); acc.w = fmaf(wa, va.w, acc.w);
        if (WITH_S) sw += wa;
    }
    #pragma unroll
    for (int o = 8; o <= 16; o <<= 1) {
        acc.x += __shfl_xor_sync(0xffffffffu, acc.x, o);
        acc.y += __shfl_xor_sync(0xffffffffu, acc.y, o);
        acc.z += __shfl_xor_sync(0xffffffffu, acc.z, o);
        acc.w += __shfl_xor_sync(0xffffffffu, acc.w, o);
        if (WITH_S) sw += __shfl_xor_sync(0xffffffffu, sw, o);
    }
    if (lane < 8)
        ((float4*)(buf + (size_t)n * 128 + DOFF))[cg] = acc;
    if (WITH_S && lane == 0) g_s[n] = sw;
}

// ---------------- gemm96 + fused log_softmax ----------------
__global__ void __launch_bounds__(256)
gemm96lsm_kernel(const float* __restrict__ X,       // H3, ld 128 (cols 0..95)
                 const float* __restrict__ W,       // 96 x 40
                 float* __restrict__ out, int nrows) {
    __shared__ float xs[16][132];
    __shared__ float ws[16][40];
    __shared__ float sbG[40], sbR[40];

    const int tid = threadIdx.x;
    const int tx  = tid & 7;
    const int ty  = tid >> 3;
    const int n0  = blockIdx.x * 128;

    if (tid < 40) { sbG[tid] = g_bG[tid]; sbR[tid] = g_bR[tid]; }

    float acc[4][5] = {};

    for (int f0 = 0; f0 < 96; f0 += 16) {
        #pragma unroll
        for (int l = 0; l < 2; ++l) {
            int idx = tid + l * 256;
            int m = idx >> 2, fq = idx & 3;
            float4 v = make_float4(0.f, 0.f, 0.f, 0.f);
            if (n0 + m < nrows)
                v = *(const float4*)&X[(size_t)(n0 + m) * 128 + f0 + fq * 4];
            xs[fq * 4 + 0][m] = v.x;
            xs[fq * 4 + 1][m] = v.y;
            xs[fq * 4 + 2][m] = v.z;
            xs[fq * 4 + 3][m] = v.w;
        }
        #pragma unroll
        for (int l = 0; l < 3; ++l) {
            int idx = tid + l * 256;
            if (idx < 640) {
                int f = idx / 40, j = idx - f * 40;
                ws[f][j] = W[(size_t)(f0 + f) * 40 + j];
            }
        }
        __syncthreads();
        #pragma unroll
        for (int f = 0; f < 16; ++f) {
            float w[5];
            #pragma unroll
            for (int c = 0; c < 5; ++c) w[c] = ws[f][tx * 5 + c];
            #pragma unroll
            for (int r = 0; r < 4; ++r) {
                float xv = xs[f][ty * 4 + r];
                #pragma unroll
                for (int c = 0; c < 5; ++c) acc[r][c] = fmaf(xv, w[c], acc[r][c]);
            }
        }
        __syncthreads();
    }

    #pragma unroll
    for (int r = 0; r < 4; ++r) {
        int n = n0 + ty * 4 + r;
        float sv = (n < nrows) ? g_s[n] : 0.f;
        float y[5];
        #pragma unroll
        for (int c = 0; c < 5; ++c) {
            int j = tx * 5 + c;
            y[c] = acc[r][c] + sv * sbG[j] + sbR[j];
        }
        float m = y[0];
        #pragma unroll
        for (int c = 1; c < 5; ++c) m = fmaxf(m, y[c]);
        #pragma unroll
        for (int o = 1; o < 8; o <<= 1) m = fmaxf(m, __shfl_xor_sync(0xffffffffu, m, o));
        float s = 0.f;
        #pragma unroll
        for (int c = 0; c < 5; ++c) s += expf(y[c] - m);
        #pragma unroll
        for (int o = 1; o < 8; o <<= 1) s += __shfl_xor_sync(0xffffffffu, s, o);
        float lse = m + logf(s);
        if (n < nrows) {
            #pragma unroll
            for (int c = 0; c < 5; ++c)
                out[(size_t)n * 40 + tx * 5 + c] = y[c] - lse;
        }
    }
}

// ---------------- launch ----------------
extern "C" void kernel_launch(void* const* d_in, const int* in_sizes, int n_in,
                              void* d_out, int out_size) {
    const float* x    = (const float*)d_in[0];
    const int*   eidx = (const int*)  d_in[1];
    const float* w1i  = (const float*)d_in[2];
    const float* w1d  = (const float*)d_in[3];
    const float* w1r  = (const float*)d_in[4];
    const float* b1   = (const float*)d_in[5];
    const float* w2i  = (const float*)d_in[6];
    const float* w2d  = (const float*)d_in[7];
    const float* w2r  = (const float*)d_in[8];
    const float* b2   = (const float*)d_in[9];
    float* outp = (float*)d_out;

    const int* row = eidx;
    const int* col = eidx + EE;

    float *A, *B, *H3, *Wp1, *W3;
    cudaGetSymbolAddress((void**)&A,   g_A);
    cudaGetSymbolAddress((void**)&B,   g_B);
    cudaGetSymbolAddress((void**)&H3,  g_H3);
    cudaGetSymbolAddress((void**)&Wp1, g_Wp1);
    cudaGetSymbolAddress((void**)&W3,  g_W3);

    static cudaStream_t s2 = nullptr;
    static cudaEvent_t  evFork = nullptr, evJoin = nullptr;
    if (s2 == nullptr) {
        cudaStreamCreateWithFlags(&s2, cudaStreamNonBlocking);
        cudaEventCreateWithFlags(&evFork, cudaEventDisableTiming);
        cudaEventCreateWithFlags(&evJoin, cudaEventDisableTiming);
    }

    const int TB = 256;
    const int nblkE4 = (EE / 4 + TB - 1) / TB;         // 782
    const int nblkW  = (NN * 32 + TB - 1) / TB;        // 6250 (warp per node)
    const int gR = (NN + 127) / 128;                   // 391 row tiles

    // init (zero deg + all weight folding) on main, then fork gemm128 to s2
    init_kernel<<<(NN + TB - 1) / TB, TB>>>(w1i, w1r, w2i, w2d, w2r, b2);
    cudaEventRecord(evFork, 0);
    cudaStreamWaitEvent(s2, evFork, 0);
    gemm128_kernel<<<gR, TB, 0, s2>>>(x, Wp1, b1, A, NN);
    cudaEventRecord(evJoin, s2);

    hist_kernel<<<nblkE4, TB>>>(col);
    scanA_kernel<<<NBLK_SCAN, 256>>>();
    scanC_kernel<<<NBLK_SCAN, 256>>>();
    fill_kernel<<<nblkE4, TB>>>(row, col);

    cudaStreamWaitEvent(0, evJoin, 0);

    // ---- conv1 ----
    prop64_kernel<<<nblkW, TB>>>(A, A + 64, B);
    prop64f_kernel<<<nblkW, TB>>>(B, A + 64, w1d, H3);       // H -> H3 cols 0..31

    // ---- conv2 (fully folded) ----
    prop32_kernel<0, 32, true ><<<nblkW, TB>>>(H3);          // PH  = A(H),  + s[n]
    prop32_kernel<32, 64, false><<<nblkW, TB>>>(H3);         // PPH = A(PH)
    gemm96lsm_kernel<<<gR, TB>>>(H3, W3, outp, NN);
}

// round 10
// speedup vs baseline: 1.6945x; 1.0371x over previous
#include <cuda_runtime.h>
#include <cuda_fp16.h>
#include <math.h>

#define NN 50000
#define EE 800000
#define NBLK_SCAN 196            // ceil(50000/256)

typedef unsigned long long u64;

// ---------------- f32x2 packed-FMA helpers (bit-identical fp32) ----------------
__device__ __forceinline__ u64 pack2(float lo, float hi) {
    u64 r; asm("mov.b64 %0, {%1, %2};" : "=l"(r) : "f"(lo), "f"(hi)); return r;
}
__device__ __forceinline__ void ffma2(u64& d, u64 a, u64 b) {
    asm("fma.rn.f32x2 %0, %1, %2, %0;" : "+l"(d) : "l"(a), "l"(b));
}
__device__ __forceinline__ float2 unpack2(u64 v) {
    float2 f; asm("mov.b64 {%0, %1}, %2;" : "=f"(f.x), "=f"(f.y) : "l"(v)); return f;
}

// 8 halves (uint4) -> 8 floats
__device__ __forceinline__ void h8_to_f8(uint4 v, float* f) {
    const __half2* h = (const __half2*)&v;
    #pragma unroll
    for (int i = 0; i < 4; ++i) {
        float2 t = __half22float2(h[i]);
        f[2 * i] = t.x; f[2 * i + 1] = t.y;
    }
}
// 8 floats -> 8 halves (uint4)
__device__ __forceinline__ uint4 f8_to_h8(const float* f) {
    uint4 v;
    __half2* h = (__half2*)&v;
    #pragma unroll
    for (int i = 0; i < 4; ++i)
        h[i] = __float22half2_rn(make_float2(f[2 * i], f[2 * i + 1]));
    return v;
}

// ---------------- scratch (device globals, no runtime alloc) ----------------
__device__ int    g_deg[NN];
__device__ int    g_off[NN + 1];
__device__ int    g_cur[NN];
__device__ float  g_dinv[NN];
__device__ int    g_part[NBLK_SCAN];
__device__ int2   g_edge[EE];              // {src, __float_as_int(ew)}
__device__ float  g_s[NN];                 // s[n] = sum of ew into n

__device__ __half g_A16[(size_t)NN * 64];  // conv1 init (fp16), ld 64
__device__ float  g_Ar [(size_t)NN * 64];  // conv1 root + b1 (fp32), ld 64
__device__ __half g_B16[(size_t)NN * 64];  // conv1 after t=0 (fp16), ld 64
__device__ float  g_H3 [(size_t)NN * 128]; // [H(0:32) | PH(32:64) | PPH(64:96) | pad]

__device__ float g_Wp1[128 * 128];         // packed [w1_init | w1_root]
__device__ float g_W3 [96 * 40];           // folded conv2 weights [WR; Wb; Wa]
__device__ float g_bG [40];                // constant-through-A bias
__device__ float g_bR [40];                // direct bias

// ---------------- init: zero degree + pack Wp1 + fold conv2 weights ----------------
__global__ void init_kernel(const float* __restrict__ w1i, const float* __restrict__ w1r,
                            const float* __restrict__ w2i, const float* __restrict__ w2d,
                            const float* __restrict__ w2r, const float* __restrict__ b2) {
    int i = blockIdx.x * blockDim.x + threadIdx.x;
    if (i < NN) g_deg[i] = 0;
    if (i < 16384) {                       // Wp1 : 128 x 128 = [w1_init | w1_root]
        int f = i >> 7, j = i & 127;
        float v;
        if (j < 64) { int k = j >> 5, h = j & 31; v = w1i[(k * 128 + f) * 32 + h]; }
        else        { int j2 = j - 64; int k = j2 >> 5, h = j2 & 31; v = w1r[(k * 128 + f) * 32 + h]; }
        g_Wp1[i] = v;
    } else if (i < 16384 + 96 * 40) {      // W3' : 96 x 40
        int i2 = i - 16384;
        int f = i2 / 40, g = i2 % 40;
        float v = 0.0f;
        if (f < 32) {
            v = 0.5f * (w2r[f * 40 + g] + w2r[(32 + f) * 40 + g]);
        } else if (f < 64) {
            int fr = f - 32;
            #pragma unroll
            for (int k = 0; k < 2; ++k) {
                float s = 0.0f;
                for (int j = 0; j < 40; ++j)
                    s = fmaf(w2r[(k * 32 + fr) * 40 + j], w2d[(k * 40 + j) * 40 + g], s);
                v += s;
            }
            v *= 0.5f;
        } else {
            int fr = f - 64;
            #pragma unroll
            for (int k = 0; k < 2; ++k) {
                float s = 0.0f;
                for (int j = 0; j < 40; ++j)
                    s = fmaf(w2i[(k * 32 + fr) * 40 + j], w2d[(k * 40 + j) * 40 + g], s);
                v += s;
            }
            v *= 0.5f;
        }
        g_W3[i2] = v;
    } else if (i < 16384 + 96 * 40 + 80) {
        int g = i - (16384 + 96 * 40);
        if (g < 40) {
            float v = 0.0f;
            #pragma unroll
            for (int k = 0; k < 2; ++k)
                for (int j = 0; j < 40; ++j)
                    v = fmaf(b2[k * 40 + j], w2d[(k * 40 + j) * 40 + g], v);
            g_bG[g] = 0.5f * v;
        } else {
            int gg = g - 40;
            g_bR[gg] = 0.5f * (b2[gg] + b2[40 + gg]);
        }
    }
}

// ---------------- hist: 4 edges per thread (int4) ----------------
__global__ void hist_kernel(const int* __restrict__ col) {
    int i = (blockIdx.x * blockDim.x + threadIdx.x) * 4;
    if (i + 4 <= EE) {
        int4 c = *(const int4*)&col[i];
        atomicAdd(&g_deg[c.x], 1);
        atomicAdd(&g_deg[c.y], 1);
        atomicAdd(&g_deg[c.z], 1);
        atomicAdd(&g_deg[c.w], 1);
    } else {
        for (; i < EE; ++i) atomicAdd(&g_deg[col[i]], 1);
    }
}

// ---------------- scan phase A: block-reduce degrees + dinv ----------------
__global__ void scanA_kernel() {
    __shared__ int sm[256];
    const int tid = threadIdx.x;
    const int i = blockIdx.x * 256 + tid;
    int d = (i < NN) ? g_deg[i] : 0;
    if (i < NN) g_dinv[i] = (d > 0) ? rsqrtf((float)d) : 0.0f;
    sm[tid] = d;
    __syncthreads();
    #pragma unroll
    for (int off = 128; off > 0; off >>= 1) {
        if (tid < off) sm[tid] += sm[tid + off];
        __syncthreads();
    }
    if (tid == 0) g_part[blockIdx.x] = sm[0];
    if (blockIdx.x == 0 && tid == 0) g_off[NN] = EE;
}

// ---------------- scan phase C: base from partials + in-block scan ----------------
__global__ void scanC_kernel() {
    __shared__ int sm[256];
    const int tid = threadIdx.x;
    const int i = blockIdx.x * 256 + tid;

    int p = (tid < blockIdx.x) ? g_part[tid] : 0;
    sm[tid] = p;
    __syncthreads();
    #pragma unroll
    for (int off = 128; off > 0; off >>= 1) {
        if (tid < off) sm[tid] += sm[tid + off];
        __syncthreads();
    }
    int base = sm[0];
    __syncthreads();

    int d = (i < NN) ? g_deg[i] : 0;
    sm[tid] = d;
    __syncthreads();
    #pragma unroll
    for (int off = 1; off < 256; off <<= 1) {
        int t = (tid >= off) ? sm[tid - off] : 0;
        __syncthreads();
        sm[tid] += t;
        __syncthreads();
    }
    if (i < NN) {
        int o = base + sm[tid] - d;
        g_off[i] = o;
        g_cur[i] = o;
    }
}

// ---------------- fill: 4 edges per thread (int4) ----------------
__global__ void fill_kernel(const int* __restrict__ row, const int* __restrict__ col) {
    int base = (blockIdx.x * blockDim.x + threadIdx.x) * 4;
    if (base + 4 <= EE) {
        int4 r = *(const int4*)&row[base];
        int4 c = *(const int4*)&col[base];
        float w0 = g_dinv[r.x] * g_dinv[c.x];
        float w1 = g_dinv[r.y] * g_dinv[c.y];
        float w2 = g_dinv[r.z] * g_dinv[c.z];
        float w3 = g_dinv[r.w] * g_dinv[c.w];
        int p0 = atomicAdd(&g_cur[c.x], 1);
        int p1 = atomicAdd(&g_cur[c.y], 1);
        int p2 = atomicAdd(&g_cur[c.z], 1);
        int p3 = atomicAdd(&g_cur[c.w], 1);
        g_edge[p0] = make_int2(r.x, __float_as_int(w0));
        g_edge[p1] = make_int2(r.y, __float_as_int(w1));
        g_edge[p2] = make_int2(r.z, __float_as_int(w2));
        g_edge[p3] = make_int2(r.w, __float_as_int(w3));
    } else {
        for (; base < EE; ++base) {
            int r0 = row[base], c0 = col[base];
            int p0 = atomicAdd(&g_cur[c0], 1);
            g_edge[p0] = make_int2(r0, __float_as_int(g_dinv[r0] * g_dinv[c0]));
        }
    }
}

// ---------------- GEMM1: [init|root+b1] = X @ Wp1; init->fp16, root->fp32 ----------------
__global__ void __launch_bounds__(256)
gemm128_kernel(const float* __restrict__ X, const float* __restrict__ W,
               const float* __restrict__ bias64,
               __half* __restrict__ A16, float* __restrict__ Ar, int nrows) {
    __shared__ float xs[16][132];
    __shared__ float ws[16][128];

    const int tid = threadIdx.x;
    const int tx  = tid & 15;
    const int ty  = tid >> 4;
    const int n0  = blockIdx.x * 128;

    u64 acc[8][4] = {};

    for (int f0 = 0; f0 < 128; f0 += 16) {
        #pragma unroll
        for (int l = 0; l < 2; ++l) {
            int idx = tid + l * 256;
            int m = idx >> 2, fq = idx & 3;
            float4 v = make_float4(0.f, 0.f, 0.f, 0.f);
            if (n0 + m < nrows)
                v = *(const float4*)&X[(size_t)(n0 + m) * 128 + f0 + fq * 4];
            xs[fq * 4 + 0][m] = v.x;
            xs[fq * 4 + 1][m] = v.y;
            xs[fq * 4 + 2][m] = v.z;
            xs[fq * 4 + 3][m] = v.w;
        }
        #pragma unroll
        for (int l = 0; l < 2; ++l) {
            int idx = tid + l * 256;
            int f = idx >> 5, j4 = idx & 31;
            *(float4*)&ws[f][j4 * 4] = *(const float4*)&W[(size_t)(f0 + f) * 128 + j4 * 4];
        }
        __syncthreads();
        #pragma unroll
        for (int f = 0; f < 16; ++f) {
            float4 xa = *(const float4*)&xs[f][ty * 8];
            float4 xb = *(const float4*)&xs[f][ty * 8 + 4];
            const u64* wp = (const u64*)&ws[f][tx * 8];
            u64 w0 = wp[0], w1 = wp[1], w2 = wp[2], w3 = wp[3];
            u64 xr;
            xr = pack2(xa.x, xa.x);
            ffma2(acc[0][0], xr, w0); ffma2(acc[0][1], xr, w1);
            ffma2(acc[0][2], xr, w2); ffma2(acc[0][3], xr, w3);
            xr = pack2(xa.y, xa.y);
            ffma2(acc[1][0], xr, w0); ffma2(acc[1][1], xr, w1);
            ffma2(acc[1][2], xr, w2); ffma2(acc[1][3], xr, w3);
            xr = pack2(xa.z, xa.z);
            ffma2(acc[2][0], xr, w0); ffma2(acc[2][1], xr, w1);
            ffma2(acc[2][2], xr, w2); ffma2(acc[2][3], xr, w3);
            xr = pack2(xa.w, xa.w);
            ffma2(acc[3][0], xr, w0); ffma2(acc[3][1], xr, w1);
            ffma2(acc[3][2], xr, w2); ffma2(acc[3][3], xr, w3);
            xr = pack2(xb.x, xb.x);
            ffma2(acc[4][0], xr, w0); ffma2(acc[4][1], xr, w1);
            ffma2(acc[4][2], xr, w2); ffma2(acc[4][3], xr, w3);
            xr = pack2(xb.y, xb.y);
            ffma2(acc[5][0], xr, w0); ffma2(acc[5][1], xr, w1);
            ffma2(acc[5][2], xr, w2); ffma2(acc[5][3], xr, w3);
            xr = pack2(xb.z, xb.z);
            ffma2(acc[6][0], xr, w0); ffma2(acc[6][1], xr, w1);
            ffma2(acc[6][2], xr, w2); ffma2(acc[6][3], xr, w3);
            xr = pack2(xb.w, xb.w);
            ffma2(acc[7][0], xr, w0); ffma2(acc[7][1], xr, w1);
            ffma2(acc[7][2], xr, w2); ffma2(acc[7][3], xr, w3);
        }
        __syncthreads();
    }

    const int jb = tx * 8;
    #pragma unroll
    for (int r = 0; r < 8; ++r) {
        int n = n0 + ty * 8 + r;
        if (n >= nrows) continue;
        float2 p0 = unpack2(acc[r][0]);
        float2 p1 = unpack2(acc[r][1]);
        float2 p2 = unpack2(acc[r][2]);
        float2 p3 = unpack2(acc[r][3]);
        float y[8] = {p0.x, p0.y, p1.x, p1.y, p2.x, p2.y, p3.x, p3.y};
        if (jb < 64) {
            // init columns -> fp16
            *(uint4*)&A16[(size_t)n * 64 + jb] = f8_to_h8(y);
        } else {
            // root columns -> fp32, + b1
            int jr = jb - 64;
            #pragma unroll
            for (int c = 0; c < 8; ++c) y[c] += bias64[jr + c];
            *(float4*)&Ar[(size_t)n * 64 + jr]     = make_float4(y[0], y[1], y[2], y[3]);
            *(float4*)&Ar[(size_t)n * 64 + jr + 4] = make_float4(y[4], y[5], y[6], y[7]);
        }
    }
}

// ---------------- prop64h: width-64 fp16 gather, fp32 math ----------------
// eg = lane>>3 (4 edges per instr), cg = lane&7 (8 halves per lane).
// Out: B16 (fp16) if !DEEP; else deep matvec -> H3 col 0..31 (fp32).
template <bool DEEP>
__global__ void __launch_bounds__(256)
prop64h_kernel(const __half* __restrict__ src,     // fp16, ld 64
               const float* __restrict__ root,     // Ar, ld 64 (includes b1)
               const float* __restrict__ w1d,      // [2][32][32] (DEEP only)
               __half* __restrict__ outB,          // B16 (if !DEEP)
               float* __restrict__ outH) {         // H3 (if DEEP), ld 128
    __shared__ float wd[2][32][32];
    __shared__ float smr[8][64];
    const int tid = threadIdx.x;
    if (DEEP) {
        #pragma unroll
        for (int l = 0; l < 8; ++l)
            ((float*)wd)[tid + l * 256] = w1d[tid + l * 256];
        __syncthreads();
    }

    const int gwarp = (blockIdx.x * blockDim.x + tid) >> 5;
    const int lane  = tid & 31;
    const int wwarp = tid >> 5;
    if (gwarp >= NN) return;
    const int n   = gwarp;
    const int beg = g_off[n];
    const int end = g_off[n + 1];
    const int eg = lane >> 3, cg = lane & 7;

    float acc[8] = {};
    int e = beg;
    for (; e + 8 <= end; e += 8) {
        int2 ea = g_edge[e + eg];
        int2 eb = g_edge[e + 4 + eg];
        uint4 va = ((const uint4*)(src + (size_t)ea.x * 64))[cg];
        uint4 vb = ((const uint4*)(src + (size_t)eb.x * 64))[cg];
        float fa[8], fb[8];
        h8_to_f8(va, fa);
        h8_to_f8(vb, fb);
        float wa = __int_as_float(ea.y), wb = __int_as_float(eb.y);
        #pragma unroll
        for (int j = 0; j < 8; ++j) {
            acc[j] = fmaf(wa, fa[j], acc[j]);
            acc[j] = fmaf(wb, fb[j], acc[j]);
        }
    }
    for (; e < end; e += 4) {
        int2 ea = (e + eg < end) ? g_edge[e + eg] : make_int2(0, 0);
        uint4 va = ((const uint4*)(src + (size_t)ea.x * 64))[cg];
        float fa[8];
        h8_to_f8(va, fa);
        float wa = __int_as_float(ea.y);
        #pragma unroll
        for (int j = 0; j < 8; ++j) acc[j] = fmaf(wa, fa[j], acc[j]);
    }
    // reduce over 4 edge groups
    #pragma unroll
    for (int j = 0; j < 8; ++j) {
        acc[j] += __shfl_xor_sync(0xffffffffu, acc[j], 8);
        acc[j] += __shfl_xor_sync(0xffffffffu, acc[j], 16);
    }

    if (!DEEP) {
        if (lane < 8) {
            const float4* rp = (const float4*)(root + (size_t)n * 64);
            float4 r0 = rp[cg * 2], r1 = rp[cg * 2 + 1];
            float y[8];
            y[0] = fmaxf(acc[0] + r0.x, 0.f); y[1] = fmaxf(acc[1] + r0.y, 0.f);
            y[2] = fmaxf(acc[2] + r0.z, 0.f); y[3] = fmaxf(acc[3] + r0.w, 0.f);
            y[4] = fmaxf(acc[4] + r1.x, 0.f); y[5] = fmaxf(acc[5] + r1.y, 0.f);
            y[6] = fmaxf(acc[6] + r1.z, 0.f); y[7] = fmaxf(acc[7] + r1.w, 0.f);
            *(uint4*)&outB[(size_t)n * 64 + cg * 8] = f8_to_h8(y);
        }
        return;
    }

    // DEEP: stage to scalar layout
    if (lane < 8) {
        #pragma unroll
        for (int j = 0; j < 8; ++j) smr[wwarp][cg * 8 + j] = acc[j];
    }
    __syncwarp();
    float a0 = smr[wwarp][lane];
    float a1 = smr[wwarp][lane + 32];

    float z0 = 0.f, z1 = 0.f;
    #pragma unroll
    for (int l = 0; l < 32; ++l) {
        float b0  = __shfl_sync(0xffffffffu, a0, l);
        float b1v = __shfl_sync(0xffffffffu, a1, l);
        z0 = fmaf(b0,  wd[0][l][lane], z0);
        z1 = fmaf(b1v, wd[1][l][lane], z1);
    }

    const float* rp = root + (size_t)n * 64;
    float y0 = fmaxf(z0 + rp[lane],      0.f);
    float y1 = fmaxf(z1 + rp[lane + 32], 0.f);
    outH[(size_t)n * 128 + lane] = 0.5f * (y0 + y1);
}

// ---------------- prop32: width-32 fp32 gather within H3 (ld 128) ----------------
template <int SOFF, int DOFF, bool WITH_S>
__global__ void prop32_kernel(float* __restrict__ buf) {
    const int gwarp = (blockIdx.x * blockDim.x + threadIdx.x) >> 5;
    const int lane  = threadIdx.x & 31;
    if (gwarp >= NN) return;
    const int n   = gwarp;
    const int beg = g_off[n];
    const int end = g_off[n + 1];
    const int eg = lane >> 3, cg = lane & 7;
    const float* src = buf + SOFF;

    float4 acc = make_float4(0.f, 0.f, 0.f, 0.f);
    float sw = 0.f;
    int e = beg;
    for (; e + 16 <= end; e += 16) {
        int2 e0 = g_edge[e + eg];
        int2 e1 = g_edge[e + 4 + eg];
        int2 e2 = g_edge[e + 8 + eg];
        int2 e3 = g_edge[e + 12 + eg];
        float4 v0 = ((const float4*)(src + (size_t)e0.x * 128))[cg];
        float4 v1 = ((const float4*)(src + (size_t)e1.x * 128))[cg];
        float4 v2 = ((const float4*)(src + (size_t)e2.x * 128))[cg];
        float4 v3 = ((const float4*)(src + (size_t)e3.x * 128))[cg];
        float w0 = __int_as_float(e0.y), w1 = __int_as_float(e1.y);
        float w2 = __int_as_float(e2.y), w3 = __int_as_float(e3.y);
        acc.x = fmaf(w0, v0.x, acc.x); acc.y = fmaf(w0, v0.y, acc.y);
        acc.z = fmaf(w0, v0.z, acc.z); acc.w = fmaf(w0, v0.w, acc.w);
        acc.x = fmaf(w1, v1.x, acc.x); acc.y = fmaf(w1, v1.y, acc.y);
        acc.z = fmaf(w1, v1.z, acc.z); acc.w = fmaf(w1, v1.w, acc.w);
        acc.x = fmaf(w2, v2.x, acc.x); acc.y = fmaf(w2, v2.y, acc.y);
        acc.z = fmaf(w2, v2.z, acc.z); acc.w = fmaf(w2, v2.w, acc.w);
        acc.x = fmaf(w3, v3.x, acc.x); acc.y = fmaf(w3, v3.y, acc.y);
        acc.z = fmaf(w3, v3.z, acc.z); acc.w = fmaf(w3, v3.w, acc.w);
        if (WITH_S) sw += w0 + w1 + w2 + w3;
    }
    for (; e < end; e += 4) {
        int2 ea = (e + eg < end) ? g_edge[e + eg] : make_int2(0, 0);
        float4 va = ((const float4*)(src + (size_t)ea.x * 128))[cg];
        float wa = __int_as_float(ea.y);
        acc.x = fmaf(wa, va.x, acc.x); acc.y = fmaf(wa, va.y, acc.y);
        acc.z = fmaf(wa, va.z, acc.z); acc.w = fmaf(wa, va.w, acc.w);
        if (WITH_S) sw += wa;
    }
    #pragma unroll
    for (int o = 8; o <= 16; o <<= 1) {
        acc.x += __shfl_xor_sync(0xffffffffu, acc.x, o);
        acc.y += __shfl_xor_sync(0xffffffffu, acc.y, o);
        acc.z += __shfl_xor_sync(0xffffffffu, acc.z, o);
        acc.w += __shfl_xor_sync(0xffffffffu, acc.w, o);
        if (WITH_S) sw += __shfl_xor_sync(0xffffffffu, sw, o);
    }
    if (lane < 8)
        ((float4*)(buf + (size_t)n * 128 + DOFF))[cg] = acc;
    if (WITH_S && lane == 0) g_s[n] = sw;
}

// ---------------- gemm96 + fused log_softmax ----------------
__global__ void __launch_bounds__(256)
gemm96lsm_kernel(const float* __restrict__ X,       // H3, ld 128 (cols 0..95)
                 const float* __restrict__ W,       // 96 x 40
                 float* __restrict__ out, int nrows) {
    __shared__ float xs[16][132];
    __shared__ float ws[16][40];
    __shared__ float sbG[40], sbR[40];

    const int tid = threadIdx.x;
    const int tx  = tid & 7;
    const int ty  = tid >> 3;
    const int n0  = blockIdx.x * 128;

    if (tid < 40) { sbG[tid] = g_bG[tid]; sbR[tid] = g_bR[tid]; }

    float acc[4][5] = {};

    for (int f0 = 0; f0 < 96; f0 += 16) {
        #pragma unroll
        for (int l = 0; l < 2; ++l) {
            int idx = tid + l * 256;
            int m = idx >> 2, fq = idx & 3;
            float4 v = make_float4(0.f, 0.f, 0.f, 0.f);
            if (n0 + m < nrows)
                v = *(const float4*)&X[(size_t)(n0 + m) * 128 + f0 + fq * 4];
            xs[fq * 4 + 0][m] = v.x;
            xs[fq * 4 + 1][m] = v.y;
            xs[fq * 4 + 2][m] = v.z;
            xs[fq * 4 + 3][m] = v.w;
        }
        #pragma unroll
        for (int l = 0; l < 3; ++l) {
            int idx = tid + l * 256;
            if (idx < 640) {
                int f = idx / 40, j = idx - f * 40;
                ws[f][j] = W[(size_t)(f0 + f) * 40 + j];
            }
        }
        __syncthreads();
        #pragma unroll
        for (int f = 0; f < 16; ++f) {
            float w[5];
            #pragma unroll
            for (int c = 0; c < 5; ++c) w[c] = ws[f][tx * 5 + c];
            #pragma unroll
            for (int r = 0; r < 4; ++r) {
                float xv = xs[f][ty * 4 + r];
                #pragma unroll
                for (int c = 0; c < 5; ++c) acc[r][c] = fmaf(xv, w[c], acc[r][c]);
            }
        }
        __syncthreads();
    }

    #pragma unroll
    for (int r = 0; r < 4; ++r) {
        int n = n0 + ty * 4 + r;
        float sv = (n < nrows) ? g_s[n] : 0.f;
        float y[5];
        #pragma unroll
        for (int c = 0; c < 5; ++c) {
            int j = tx * 5 + c;
            y[c] = acc[r][c] + sv * sbG[j] + sbR[j];
        }
        float m = y[0];
        #pragma unroll
        for (int c = 1; c < 5; ++c) m = fmaxf(m, y[c]);
        #pragma unroll
        for (int o = 1; o < 8; o <<= 1) m = fmaxf(m, __shfl_xor_sync(0xffffffffu, m, o));
        float s = 0.f;
        #pragma unroll
        for (int c = 0; c < 5; ++c) s += expf(y[c] - m);
        #pragma unroll
        for (int o = 1; o < 8; o <<= 1) s += __shfl_xor_sync(0xffffffffu, s, o);
        float lse = m + logf(s);
        if (n < nrows) {
            #pragma unroll
            for (int c = 0; c < 5; ++c)
                out[(size_t)n * 40 + tx * 5 + c] = y[c] - lse;
        }
    }
}

// ---------------- launch ----------------
extern "C" void kernel_launch(void* const* d_in, const int* in_sizes, int n_in,
                              void* d_out, int out_size) {
    const float* x    = (const float*)d_in[0];
    const int*   eidx = (const int*)  d_in[1];
    const float* w1i  = (const float*)d_in[2];
    const float* w1d  = (const float*)d_in[3];
    const float* w1r  = (const float*)d_in[4];
    const float* b1   = (const float*)d_in[5];
    const float* w2i  = (const float*)d_in[6];
    const float* w2d  = (const float*)d_in[7];
    const float* w2r  = (const float*)d_in[8];
    const float* b2   = (const float*)d_in[9];
    float* outp = (float*)d_out;

    const int* row = eidx;
    const int* col = eidx + EE;

    __half *A16, *B16;
    float *Ar, *H3, *Wp1, *W3;
    cudaGetSymbolAddress((void**)&A16, g_A16);
    cudaGetSymbolAddress((void**)&Ar,  g_Ar);
    cudaGetSymbolAddress((void**)&B16, g_B16);
    cudaGetSymbolAddress((void**)&H3,  g_H3);
    cudaGetSymbolAddress((void**)&Wp1, g_Wp1);
    cudaGetSymbolAddress((void**)&W3,  g_W3);

    static cudaStream_t s2 = nullptr;
    static cudaEvent_t  evFork = nullptr, evJoin = nullptr;
    if (s2 == nullptr) {
        cudaStreamCreateWithFlags(&s2, cudaStreamNonBlocking);
        cudaEventCreateWithFlags(&evFork, cudaEventDisableTiming);
        cudaEventCreateWithFlags(&evJoin, cudaEventDisableTiming);
    }

    const int TB = 256;
    const int nblkE4 = (EE / 4 + TB - 1) / TB;         // 782
    const int nblkW  = (NN * 32 + TB - 1) / TB;        // 6250 (warp per node)
    const int gR = (NN + 127) / 128;                   // 391 row tiles

    init_kernel<<<(NN + TB - 1) / TB, TB>>>(w1i, w1r, w2i, w2d, w2r, b2);
    cudaEventRecord(evFork, 0);
    cudaStreamWaitEvent(s2, evFork, 0);
    gemm128_kernel<<<gR, TB, 0, s2>>>(x, Wp1, b1, A16, Ar, NN);
    cudaEventRecord(evJoin, s2);

    hist_kernel<<<nblkE4, TB>>>(col);
    scanA_kernel<<<NBLK_SCAN, 256>>>();
    scanC_kernel<<<NBLK_SCAN, 256>>>();
    fill_kernel<<<nblkE4, TB>>>(row, col);

    cudaStreamWaitEvent(0, evJoin, 0);

    // ---- conv1 (fp16 gathers, fp32 math) ----
    prop64h_kernel<false><<<nblkW, TB>>>(A16, Ar, nullptr, B16, nullptr);
    prop64h_kernel<true ><<<nblkW, TB>>>(B16, Ar, w1d, nullptr, H3);   // H -> H3 cols 0..31

    // ---- conv2 (fully folded, fp32) ----
    prop32_kernel<0, 32, true ><<<nblkW, TB>>>(H3);          // PH  = A(H),  + s[n]
    prop32_kernel<32, 64, false><<<nblkW, TB>>>(H3);         // PPH = A(PH)
    gemm96lsm_kernel<<<gR, TB>>>(H3, W3, outp, NN);
}

// round 11
// speedup vs baseline: 1.6980x; 1.0020x over previous
#include <cuda_runtime.h>
#include <cuda_fp16.h>
#include <math.h>

#define NN 50000
#define EE 800000
#define NBLK_SCAN 196            // ceil(50000/256)

typedef unsigned long long u64;

// ---------------- f32x2 packed-FMA helpers (bit-identical fp32) ----------------
__device__ __forceinline__ u64 pack2(float lo, float hi) {
    u64 r; asm("mov.b64 %0, {%1, %2};" : "=l"(r) : "f"(lo), "f"(hi)); return r;
}
__device__ __forceinline__ void ffma2(u64& d, u64 a, u64 b) {
    asm("fma.rn.f32x2 %0, %1, %2, %0;" : "+l"(d) : "l"(a), "l"(b));
}
__device__ __forceinline__ float2 unpack2(u64 v) {
    float2 f; asm("mov.b64 {%0, %1}, %2;" : "=f"(f.x), "=f"(f.y) : "l"(v)); return f;
}

// 8 halves (uint4) -> 8 floats
__device__ __forceinline__ void h8_to_f8(uint4 v, float* f) {
    const __half2* h = (const __half2*)&v;
    #pragma unroll
    for (int i = 0; i < 4; ++i) {
        float2 t = __half22float2(h[i]);
        f[2 * i] = t.x; f[2 * i + 1] = t.y;
    }
}
// 8 floats -> 8 halves (uint4)
__device__ __forceinline__ uint4 f8_to_h8(const float* f) {
    uint4 v;
    __half2* h = (__half2*)&v;
    #pragma unroll
    for (int i = 0; i < 4; ++i)
        h[i] = __float22half2_rn(make_float2(f[2 * i], f[2 * i + 1]));
    return v;
}

// ---------------- scratch (device globals, no runtime alloc) ----------------
__device__ int    g_deg[NN];
__device__ int    g_off[NN + 1];
__device__ int    g_cur[NN];
__device__ float  g_dinv[NN];
__device__ int    g_part[NBLK_SCAN];
__device__ int2   g_edge[EE];              // {src, __float_as_int(ew)}
__device__ float  g_s[NN];                 // s[n] = sum of ew into n

__device__ __half g_A16[(size_t)NN * 64];  // conv1 init (fp16), ld 64
__device__ float  g_Ar [(size_t)NN * 64];  // conv1 root + b1 (fp32), ld 64
__device__ __half g_B16[(size_t)NN * 64];  // conv1 after t=0 (fp16), ld 64
__device__ __half g_H16[(size_t)NN * 128]; // [H(0:32)|PH(32:64)|PPH(64:96)|pad], fp16

__device__ float g_Wp1[128 * 128];         // packed [w1_init | w1_root]
__device__ float g_W3 [96 * 40];           // folded conv2 weights [WR; Wb; Wa]
__device__ float g_bG [40];                // constant-through-A bias
__device__ float g_bR [40];                // direct bias

// ---------------- init: zero degree + pack Wp1 + fold conv2 weights ----------------
__global__ void init_kernel(const float* __restrict__ w1i, const float* __restrict__ w1r,
                            const float* __restrict__ w2i, const float* __restrict__ w2d,
                            const float* __restrict__ w2r, const float* __restrict__ b2) {
    int i = blockIdx.x * blockDim.x + threadIdx.x;
    if (i < NN) g_deg[i] = 0;
    if (i < 16384) {                       // Wp1 : 128 x 128 = [w1_init | w1_root]
        int f = i >> 7, j = i & 127;
        float v;
        if (j < 64) { int k = j >> 5, h = j & 31; v = w1i[(k * 128 + f) * 32 + h]; }
        else        { int j2 = j - 64; int k = j2 >> 5, h = j2 & 31; v = w1r[(k * 128 + f) * 32 + h]; }
        g_Wp1[i] = v;
    } else if (i < 16384 + 96 * 40) {      // W3' : 96 x 40
        int i2 = i - 16384;
        int f = i2 / 40, g = i2 % 40;
        float v = 0.0f;
        if (f < 32) {
            v = 0.5f * (w2r[f * 40 + g] + w2r[(32 + f) * 40 + g]);
        } else if (f < 64) {
            int fr = f - 32;
            #pragma unroll
            for (int k = 0; k < 2; ++k) {
                float s = 0.0f;
                for (int j = 0; j < 40; ++j)
                    s = fmaf(w2r[(k * 32 + fr) * 40 + j], w2d[(k * 40 + j) * 40 + g], s);
                v += s;
            }
            v *= 0.5f;
        } else {
            int fr = f - 64;
            #pragma unroll
            for (int k = 0; k < 2; ++k) {
                float s = 0.0f;
                for (int j = 0; j < 40; ++j)
                    s = fmaf(w2i[(k * 32 + fr) * 40 + j], w2d[(k * 40 + j) * 40 + g], s);
                v += s;
            }
            v *= 0.5f;
        }
        g_W3[i2] = v;
    } else if (i < 16384 + 96 * 40 + 80) {
        int g = i - (16384 + 96 * 40);
        if (g < 40) {
            float v = 0.0f;
            #pragma unroll
            for (int k = 0; k < 2; ++k)
                for (int j = 0; j < 40; ++j)
                    v = fmaf(b2[k * 40 + j], w2d[(k * 40 + j) * 40 + g], v);
            g_bG[g] = 0.5f * v;
        } else {
            int gg = g - 40;
            g_bR[gg] = 0.5f * (b2[gg] + b2[40 + gg]);
        }
    }
}

// ---------------- hist: 4 edges per thread (int4) ----------------
__global__ void hist_kernel(const int* __restrict__ col) {
    int i = (blockIdx.x * blockDim.x + threadIdx.x) * 4;
    if (i + 4 <= EE) {
        int4 c = *(const int4*)&col[i];
        atomicAdd(&g_deg[c.x], 1);
        atomicAdd(&g_deg[c.y], 1);
        atomicAdd(&g_deg[c.z], 1);
        atomicAdd(&g_deg[c.w], 1);
    } else {
        for (; i < EE; ++i) atomicAdd(&g_deg[col[i]], 1);
    }
}

// ---------------- scan phase A: block-reduce degrees + dinv ----------------
__global__ void scanA_kernel() {
    __shared__ int sm[256];
    const int tid = threadIdx.x;
    const int i = blockIdx.x * 256 + tid;
    int d = (i < NN) ? g_deg[i] : 0;
    if (i < NN) g_dinv[i] = (d > 0) ? rsqrtf((float)d) : 0.0f;
    sm[tid] = d;
    __syncthreads();
    #pragma unroll
    for (int off = 128; off > 0; off >>= 1) {
        if (tid < off) sm[tid] += sm[tid + off];
        __syncthreads();
    }
    if (tid == 0) g_part[blockIdx.x] = sm[0];
    if (blockIdx.x == 0 && tid == 0) g_off[NN] = EE;
}

// ---------------- scan phase C: base from partials + in-block scan ----------------
__global__ void scanC_kernel() {
    __shared__ int sm[256];
    const int tid = threadIdx.x;
    const int i = blockIdx.x * 256 + tid;

    int p = (tid < blockIdx.x) ? g_part[tid] : 0;
    sm[tid] = p;
    __syncthreads();
    #pragma unroll
    for (int off = 128; off > 0; off >>= 1) {
        if (tid < off) sm[tid] += sm[tid + off];
        __syncthreads();
    }
    int base = sm[0];
    __syncthreads();

    int d = (i < NN) ? g_deg[i] : 0;
    sm[tid] = d;
    __syncthreads();
    #pragma unroll
    for (int off = 1; off < 256; off <<= 1) {
        int t = (tid >= off) ? sm[tid - off] : 0;
        __syncthreads();
        sm[tid] += t;
        __syncthreads();
    }
    if (i < NN) {
        int o = base + sm[tid] - d;
        g_off[i] = o;
        g_cur[i] = o;
    }
}

// ---------------- fill: 4 edges per thread (int4) ----------------
__global__ void fill_kernel(const int* __restrict__ row, const int* __restrict__ col) {
    int base = (blockIdx.x * blockDim.x + threadIdx.x) * 4;
    if (base + 4 <= EE) {
        int4 r = *(const int4*)&row[base];
        int4 c = *(const int4*)&col[base];
        float w0 = g_dinv[r.x] * g_dinv[c.x];
        float w1 = g_dinv[r.y] * g_dinv[c.y];
        float w2 = g_dinv[r.z] * g_dinv[c.z];
        float w3 = g_dinv[r.w] * g_dinv[c.w];
        int p0 = atomicAdd(&g_cur[c.x], 1);
        int p1 = atomicAdd(&g_cur[c.y], 1);
        int p2 = atomicAdd(&g_cur[c.z], 1);
        int p3 = atomicAdd(&g_cur[c.w], 1);
        g_edge[p0] = make_int2(r.x, __float_as_int(w0));
        g_edge[p1] = make_int2(r.y, __float_as_int(w1));
        g_edge[p2] = make_int2(r.z, __float_as_int(w2));
        g_edge[p3] = make_int2(r.w, __float_as_int(w3));
    } else {
        for (; base < EE; ++base) {
            int r0 = row[base], c0 = col[base];
            int p0 = atomicAdd(&g_cur[c0], 1);
            g_edge[p0] = make_int2(r0, __float_as_int(g_dinv[r0] * g_dinv[c0]));
        }
    }
}

// ---------------- GEMM1: [init|root+b1] = X @ Wp1; init->fp16, root->fp32 ----------------
__global__ void __launch_bounds__(256)
gemm128_kernel(const float* __restrict__ X, const float* __restrict__ W,
               const float* __restrict__ bias64,
               __half* __restrict__ A16, float* __restrict__ Ar, int nrows) {
    __shared__ float xs[16][132];
    __shared__ float ws[16][128];

    const int tid = threadIdx.x;
    const int tx  = tid & 15;
    const int ty  = tid >> 4;
    const int n0  = blockIdx.x * 128;

    u64 acc[8][4] = {};

    for (int f0 = 0; f0 < 128; f0 += 16) {
        #pragma unroll
        for (int l = 0; l < 2; ++l) {
            int idx = tid + l * 256;
            int m = idx >> 2, fq = idx & 3;
            float4 v = make_float4(0.f, 0.f, 0.f, 0.f);
            if (n0 + m < nrows)
                v = *(const float4*)&X[(size_t)(n0 + m) * 128 + f0 + fq * 4];
            xs[fq * 4 + 0][m] = v.x;
            xs[fq * 4 + 1][m] = v.y;
            xs[fq * 4 + 2][m] = v.z;
            xs[fq * 4 + 3][m] = v.w;
        }
        #pragma unroll
        for (int l = 0; l < 2; ++l) {
            int idx = tid + l * 256;
            int f = idx >> 5, j4 = idx & 31;
            *(float4*)&ws[f][j4 * 4] = *(const float4*)&W[(size_t)(f0 + f) * 128 + j4 * 4];
        }
        __syncthreads();
        #pragma unroll
        for (int f = 0; f < 16; ++f) {
            float4 xa = *(const float4*)&xs[f][ty * 8];
            float4 xb = *(const float4*)&xs[f][ty * 8 + 4];
            const u64* wp = (const u64*)&ws[f][tx * 8];
            u64 w0 = wp[0], w1 = wp[1], w2 = wp[2], w3 = wp[3];
            u64 xr;
            xr = pack2(xa.x, xa.x);
            ffma2(acc[0][0], xr, w0); ffma2(acc[0][1], xr, w1);
            ffma2(acc[0][2], xr, w2); ffma2(acc[0][3], xr, w3);
            xr = pack2(xa.y, xa.y);
            ffma2(acc[1][0], xr, w0); ffma2(acc[1][1], xr, w1);
            ffma2(acc[1][2], xr, w2); ffma2(acc[1][3], xr, w3);
            xr = pack2(xa.z, xa.z);
            ffma2(acc[2][0], xr, w0); ffma2(acc[2][1], xr, w1);
            ffma2(acc[2][2], xr, w2); ffma2(acc[2][3], xr, w3);
            xr = pack2(xa.w, xa.w);
            ffma2(acc[3][0], xr, w0); ffma2(acc[3][1], xr, w1);
            ffma2(acc[3][2], xr, w2); ffma2(acc[3][3], xr, w3);
            xr = pack2(xb.x, xb.x);
            ffma2(acc[4][0], xr, w0); ffma2(acc[4][1], xr, w1);
            ffma2(acc[4][2], xr, w2); ffma2(acc[4][3], xr, w3);
            xr = pack2(xb.y, xb.y);
            ffma2(acc[5][0], xr, w0); ffma2(acc[5][1], xr, w1);
            ffma2(acc[5][2], xr, w2); ffma2(acc[5][3], xr, w3);
            xr = pack2(xb.z, xb.z);
            ffma2(acc[6][0], xr, w0); ffma2(acc[6][1], xr, w1);
            ffma2(acc[6][2], xr, w2); ffma2(acc[6][3], xr, w3);
            xr = pack2(xb.w, xb.w);
            ffma2(acc[7][0], xr, w0); ffma2(acc[7][1], xr, w1);
            ffma2(acc[7][2], xr, w2); ffma2(acc[7][3], xr, w3);
        }
        __syncthreads();
    }

    const int jb = tx * 8;
    #pragma unroll
    for (int r = 0; r < 8; ++r) {
        int n = n0 + ty * 8 + r;
        if (n >= nrows) continue;
        float2 p0 = unpack2(acc[r][0]);
        float2 p1 = unpack2(acc[r][1]);
        float2 p2 = unpack2(acc[r][2]);
        float2 p3 = unpack2(acc[r][3]);
        float y[8] = {p0.x, p0.y, p1.x, p1.y, p2.x, p2.y, p3.x, p3.y};
        if (jb < 64) {
            *(uint4*)&A16[(size_t)n * 64 + jb] = f8_to_h8(y);
        } else {
            int jr = jb - 64;
            #pragma unroll
            for (int c = 0; c < 8; ++c) y[c] += bias64[jr + c];
            *(float4*)&Ar[(size_t)n * 64 + jr]     = make_float4(y[0], y[1], y[2], y[3]);
            *(float4*)&Ar[(size_t)n * 64 + jr + 4] = make_float4(y[4], y[5], y[6], y[7]);
        }
    }
}

// ---------------- prop64h: width-64 fp16 gather, fp32 math ----------------
// eg = lane>>3 (4 edges per instr), cg = lane&7 (8 halves per lane).
// !DEEP: -> B16 (fp16). DEEP: deep matvec -> H16 cols 0..31 (fp16).
template <bool DEEP>
__global__ void __launch_bounds__(256)
prop64h_kernel(const __half* __restrict__ src,     // fp16, ld 64
               const float* __restrict__ root,     // Ar, ld 64 (includes b1)
               const float* __restrict__ w1d,      // [2][32][32] (DEEP only)
               __half* __restrict__ outB,          // B16 (if !DEEP)
               __half* __restrict__ outH) {        // H16 (if DEEP), ld 128
    __shared__ float wd[2][32][32];
    __shared__ float smr[8][64];
    const int tid = threadIdx.x;
    if (DEEP) {
        #pragma unroll
        for (int l = 0; l < 8; ++l)
            ((float*)wd)[tid + l * 256] = w1d[tid + l * 256];
        __syncthreads();
    }

    const int gwarp = (blockIdx.x * blockDim.x + tid) >> 5;
    const int lane  = tid & 31;
    const int wwarp = tid >> 5;
    if (gwarp >= NN) return;
    const int n   = gwarp;
    const int beg = g_off[n];
    const int end = g_off[n + 1];
    const int eg = lane >> 3, cg = lane & 7;

    float acc[8] = {};
    int e = beg;
    for (; e + 8 <= end; e += 8) {
        int2 ea = g_edge[e + eg];
        int2 eb = g_edge[e + 4 + eg];
        uint4 va = ((const uint4*)(src + (size_t)ea.x * 64))[cg];
        uint4 vb = ((const uint4*)(src + (size_t)eb.x * 64))[cg];
        float fa[8], fb[8];
        h8_to_f8(va, fa);
        h8_to_f8(vb, fb);
        float wa = __int_as_float(ea.y), wb = __int_as_float(eb.y);
        #pragma unroll
        for (int j = 0; j < 8; ++j) {
            acc[j] = fmaf(wa, fa[j], acc[j]);
            acc[j] = fmaf(wb, fb[j], acc[j]);
        }
    }
    for (; e < end; e += 4) {
        int2 ea = (e + eg < end) ? g_edge[e + eg] : make_int2(0, 0);
        uint4 va = ((const uint4*)(src + (size_t)ea.x * 64))[cg];
        float fa[8];
        h8_to_f8(va, fa);
        float wa = __int_as_float(ea.y);
        #pragma unroll
        for (int j = 0; j < 8; ++j) acc[j] = fmaf(wa, fa[j], acc[j]);
    }
    #pragma unroll
    for (int j = 0; j < 8; ++j) {
        acc[j] += __shfl_xor_sync(0xffffffffu, acc[j], 8);
        acc[j] += __shfl_xor_sync(0xffffffffu, acc[j], 16);
    }

    if (!DEEP) {
        if (lane < 8) {
            const float4* rp = (const float4*)(root + (size_t)n * 64);
            float4 r0 = rp[cg * 2], r1 = rp[cg * 2 + 1];
            float y[8];
            y[0] = fmaxf(acc[0] + r0.x, 0.f); y[1] = fmaxf(acc[1] + r0.y, 0.f);
            y[2] = fmaxf(acc[2] + r0.z, 0.f); y[3] = fmaxf(acc[3] + r0.w, 0.f);
            y[4] = fmaxf(acc[4] + r1.x, 0.f); y[5] = fmaxf(acc[5] + r1.y, 0.f);
            y[6] = fmaxf(acc[6] + r1.z, 0.f); y[7] = fmaxf(acc[7] + r1.w, 0.f);
            *(uint4*)&outB[(size_t)n * 64 + cg * 8] = f8_to_h8(y);
        }
        return;
    }

    if (lane < 8) {
        #pragma unroll
        for (int j = 0; j < 8; ++j) smr[wwarp][cg * 8 + j] = acc[j];
    }
    __syncwarp();
    float a0 = smr[wwarp][lane];
    float a1 = smr[wwarp][lane + 32];

    float z0 = 0.f, z1 = 0.f;
    #pragma unroll
    for (int l = 0; l < 32; ++l) {
        float b0  = __shfl_sync(0xffffffffu, a0, l);
        float b1v = __shfl_sync(0xffffffffu, a1, l);
        z0 = fmaf(b0,  wd[0][l][lane], z0);
        z1 = fmaf(b1v, wd[1][l][lane], z1);
    }

    const float* rp = root + (size_t)n * 64;
    float y0 = fmaxf(z0 + rp[lane],      0.f);
    float y1 = fmaxf(z1 + rp[lane + 32], 0.f);
    outH[(size_t)n * 128 + lane] = __float2half_rn(0.5f * (y0 + y1));
}

// ---------------- prop32h: width-32 fp16 gather within H16 (ld 128) ----------------
// eg = lane>>2 (8 edges per instr), cg = lane&3 (8 halves per lane).
template <int SOFF, int DOFF, bool WITH_S>
__global__ void prop32h_kernel(__half* __restrict__ buf) {
    const int gwarp = (blockIdx.x * blockDim.x + threadIdx.x) >> 5;
    const int lane  = threadIdx.x & 31;
    if (gwarp >= NN) return;
    const int n   = gwarp;
    const int beg = g_off[n];
    const int end = g_off[n + 1];
    const int eg = lane >> 2, cg = lane & 3;
    const __half* src = buf + SOFF;

    float acc[8] = {};
    float sw = 0.f;
    int e = beg;
    for (; e + 16 <= end; e += 16) {
        int2 ea = g_edge[e + eg];
        int2 eb = g_edge[e + 8 + eg];
        uint4 va = ((const uint4*)(src + (size_t)ea.x * 128))[cg];
        uint4 vb = ((const uint4*)(src + (size_t)eb.x * 128))[cg];
        float fa[8], fb[8];
        h8_to_f8(va, fa);
        h8_to_f8(vb, fb);
        float wa = __int_as_float(ea.y), wb = __int_as_float(eb.y);
        #pragma unroll
        for (int j = 0; j < 8; ++j) {
            acc[j] = fmaf(wa, fa[j], acc[j]);
            acc[j] = fmaf(wb, fb[j], acc[j]);
        }
        if (WITH_S) sw += wa + wb;
    }
    for (; e < end; e += 8) {
        int2 ea = (e + eg < end) ? g_edge[e + eg] : make_int2(0, 0);
        uint4 va = ((const uint4*)(src + (size_t)ea.x * 128))[cg];
        float fa[8];
        h8_to_f8(va, fa);
        float wa = __int_as_float(ea.y);
        #pragma unroll
        for (int j = 0; j < 8; ++j) acc[j] = fmaf(wa, fa[j], acc[j]);
        if (WITH_S) sw += wa;
    }
    // reduce over 8 edge groups
    #pragma unroll
    for (int j = 0; j < 8; ++j) {
        acc[j] += __shfl_xor_sync(0xffffffffu, acc[j], 4);
        acc[j] += __shfl_xor_sync(0xffffffffu, acc[j], 8);
        acc[j] += __shfl_xor_sync(0xffffffffu, acc[j], 16);
    }
    if (WITH_S) {
        sw += __shfl_xor_sync(0xffffffffu, sw, 4);
        sw += __shfl_xor_sync(0xffffffffu, sw, 8);
        sw += __shfl_xor_sync(0xffffffffu, sw, 16);
    }
    if (lane < 4)
        *(uint4*)&buf[(size_t)n * 128 + DOFF + cg * 8] = f8_to_h8(acc);
    if (WITH_S && lane == 0) g_s[n] = sw;
}

// ---------------- gemm96 (fp16 X) + fused log_softmax ----------------
__global__ void __launch_bounds__(256)
gemm96lsm_kernel(const __half* __restrict__ X,      // H16, ld 128 (cols 0..95)
                 const float* __restrict__ W,       // 96 x 40
                 float* __restrict__ out, int nrows) {
    __shared__ float xs[16][132];
    __shared__ float ws[16][40];
    __shared__ float sbG[40], sbR[40];

    const int tid = threadIdx.x;
    const int tx  = tid & 7;
    const int ty  = tid >> 3;
    const int n0  = blockIdx.x * 128;

    if (tid < 40) { sbG[tid] = g_bG[tid]; sbR[tid] = g_bR[tid]; }

    float acc[4][5] = {};

    for (int f0 = 0; f0 < 96; f0 += 16) {
        {
            int m = tid >> 1, q = tid & 1;       // 128 rows x 2 groups of 8 halves
            uint4 v = make_uint4(0, 0, 0, 0);
            if (n0 + m < nrows)
                v = *(const uint4*)&X[(size_t)(n0 + m) * 128 + f0 + q * 8];
            float fv[8];
            h8_to_f8(v, fv);
            #pragma unroll
            for (int j = 0; j < 8; ++j) xs[q * 8 + j][m] = fv[j];
        }
        #pragma unroll
        for (int l = 0; l < 3; ++l) {
            int idx = tid + l * 256;
            if (idx < 640) {
                int f = idx / 40, j = idx - f * 40;
                ws[f][j] = W[(size_t)(f0 + f) * 40 + j];
            }
        }
        __syncthreads();
        #pragma unroll
        for (int f = 0; f < 16; ++f) {
            float w[5];
            #pragma unroll
            for (int c = 0; c < 5; ++c) w[c] = ws[f][tx * 5 + c];
            #pragma unroll
            for (int r = 0; r < 4; ++r) {
                float xv = xs[f][ty * 4 + r];
                #pragma unroll
                for (int c = 0; c < 5; ++c) acc[r][c] = fmaf(xv, w[c], acc[r][c]);
            }
        }
        __syncthreads();
    }

    #pragma unroll
    for (int r = 0; r < 4; ++r) {
        int n = n0 + ty * 4 + r;
        float sv = (n < nrows) ? g_s[n] : 0.f;
        float y[5];
        #pragma unroll
        for (int c = 0; c < 5; ++c) {
            int j = tx * 5 + c;
            y[c] = acc[r][c] + sv * sbG[j] + sbR[j];
        }
        float m = y[0];
        #pragma unroll
        for (int c = 1; c < 5; ++c) m = fmaxf(m, y[c]);
        #pragma unroll
        for (int o = 1; o < 8; o <<= 1) m = fmaxf(m, __shfl_xor_sync(0xffffffffu, m, o));
        float s = 0.f;
        #pragma unroll
        for (int c = 0; c < 5; ++c) s += expf(y[c] - m);
        #pragma unroll
        for (int o = 1; o < 8; o <<= 1) s += __shfl_xor_sync(0xffffffffu, s, o);
        float lse = m + logf(s);
        if (n < nrows) {
            #pragma unroll
            for (int c = 0; c < 5; ++c)
                out[(size_t)n * 40 + tx * 5 + c] = y[c] - lse;
        }
    }
}

// ---------------- launch ----------------
extern "C" void kernel_launch(void* const* d_in, const int* in_sizes, int n_in,
                              void* d_out, int out_size) {
    const float* x    = (const float*)d_in[0];
    const int*   eidx = (const int*)  d_in[1];
    const float* w1i  = (const float*)d_in[2];
    const float* w1d  = (const float*)d_in[3];
    const float* w1r  = (const float*)d_in[4];
    const float* b1   = (const float*)d_in[5];
    const float* w2i  = (const float*)d_in[6];
    const float* w2d  = (const float*)d_in[7];
    const float* w2r  = (const float*)d_in[8];
    const float* b2   = (const float*)d_in[9];
    float* outp = (float*)d_out;

    const int* row = eidx;
    const int* col = eidx + EE;

    __half *A16, *B16, *H16;
    float *Ar, *Wp1, *W3;
    cudaGetSymbolAddress((void**)&A16, g_A16);
    cudaGetSymbolAddress((void**)&Ar,  g_Ar);
    cudaGetSymbolAddress((void**)&B16, g_B16);
    cudaGetSymbolAddress((void**)&H16, g_H16);
    cudaGetSymbolAddress((void**)&Wp1, g_Wp1);
    cudaGetSymbolAddress((void**)&W3,  g_W3);

    static cudaStream_t s2 = nullptr;
    static cudaEvent_t  evFork = nullptr, evJoin = nullptr;
    if (s2 == nullptr) {
        cudaStreamCreateWithFlags(&s2, cudaStreamNonBlocking);
        cudaEventCreateWithFlags(&evFork, cudaEventDisableTiming);
        cudaEventCreateWithFlags(&evJoin, cudaEventDisableTiming);
    }

    const int TB = 256;
    const int nblkE4 = (EE / 4 + TB - 1) / TB;         // 782
    const int nblkW  = (NN * 32 + TB - 1) / TB;        // 6250 (warp per node)
    const int gR = (NN + 127) / 128;                   // 391 row tiles

    init_kernel<<<(NN + TB - 1) / TB, TB>>>(w1i, w1r, w2i, w2d, w2r, b2);
    cudaEventRecord(evFork, 0);
    cudaStreamWaitEvent(s2, evFork, 0);
    gemm128_kernel<<<gR, TB, 0, s2>>>(x, Wp1, b1, A16, Ar, NN);
    cudaEventRecord(evJoin, s2);

    hist_kernel<<<nblkE4, TB>>>(col);
    scanA_kernel<<<NBLK_SCAN, 256>>>();
    scanC_kernel<<<NBLK_SCAN, 256>>>();
    fill_kernel<<<nblkE4, TB>>>(row, col);

    cudaStreamWaitEvent(0, evJoin, 0);

    // ---- conv1 (fp16 gathers, fp32 math) ----
    prop64h_kernel<false><<<nblkW, TB>>>(A16, Ar, nullptr, B16, nullptr);
    prop64h_kernel<true ><<<nblkW, TB>>>(B16, Ar, w1d, nullptr, H16);  // H -> H16 cols 0..31

    // ---- conv2 (fully folded, fp16 features) ----
    prop32h_kernel<0, 32, true ><<<nblkW, TB>>>(H16);        // PH  = A(H),  + s[n]
    prop32h_kernel<32, 64, false><<<nblkW, TB>>>(H16);       // PPH = A(PH)
    gemm96lsm_kernel<<<gR, TB>>>(H16, W3, outp, NN);
}